// round 2
// baseline (speedup 1.0000x reference)
#include <cuda_runtime.h>
#include <math.h>

#define BB 4
#define TT 1024
#define CCH 1024
#define HH 16
#define DD 64
#define NKC 16
#define SCALE_F 0.125f

// Scratch (device globals: allocation-free rule)
__device__ float g_q[BB * HH * TT * DD];
__device__ float g_k[BB * HH * TT * DD];
__device__ float g_v[BB * HH * TT * DD];
__device__ float g_attn[BB * TT * CCH];

__device__ __forceinline__ float4 ld4(const float* p) {
    return *reinterpret_cast<const float4*>(p);
}

__device__ __forceinline__ float nan2num(float v) {
    if (isnan(v)) return 0.f;
    if (isinf(v)) return v > 0.f ? 1.f : -1.f;
    return v;
}

// ---------------------------------------------------------------------------
// SGEMM 128x128x8, 256 threads, 8x8 register tile. M=4096, N=1024, K=1024.
// Projections: out goes to g_q/g_k/g_v in [B][H][T][D] layout.
// ---------------------------------------------------------------------------
__global__ __launch_bounds__(256) void proj_kernel(
    const float* __restrict__ x,
    const float* __restrict__ Wq,
    const float* __restrict__ Wk,
    const float* __restrict__ Wv)
{
    __shared__ float As[8][128];
    __shared__ float Bs[8][128];

    const int tid = threadIdx.x;
    const int m0 = blockIdx.y * 128;
    const int n0 = blockIdx.x * 128;
    const float* W = (blockIdx.z == 0) ? Wq : (blockIdx.z == 1) ? Wk : Wv;
    float* dst     = (blockIdx.z == 0) ? g_q : (blockIdx.z == 1) ? g_k : g_v;

    const int arow = tid >> 1, acol = (tid & 1) * 4;
    const int brow = tid >> 5, bcol = (tid & 31) * 4;
    const float* Ap = x + (m0 + arow) * CCH + acol;
    const float* Bp = W + brow * CCH + n0 + bcol;

    float acc[8][8];
#pragma unroll
    for (int i = 0; i < 8; i++)
#pragma unroll
        for (int j = 0; j < 8; j++) acc[i][j] = 0.f;

    const int ty = tid >> 4, tx = tid & 15;

#pragma unroll 1
    for (int kt = 0; kt < CCH; kt += 8) {
        float4 av = ld4(Ap + kt);
        float4 bv = ld4(Bp + kt * CCH);
        As[acol + 0][arow] = av.x;
        As[acol + 1][arow] = av.y;
        As[acol + 2][arow] = av.z;
        As[acol + 3][arow] = av.w;
        *reinterpret_cast<float4*>(&Bs[brow][bcol]) = bv;
        __syncthreads();
#pragma unroll
        for (int k = 0; k < 8; k++) {
            float a[8], b[8];
            *(float4*)&a[0] = *(const float4*)&As[k][ty * 8];
            *(float4*)&a[4] = *(const float4*)&As[k][ty * 8 + 4];
            *(float4*)&b[0] = *(const float4*)&Bs[k][tx * 8];
            *(float4*)&b[4] = *(const float4*)&Bs[k][tx * 8 + 4];
#pragma unroll
            for (int i = 0; i < 8; i++)
#pragma unroll
                for (int j = 0; j < 8; j++)
                    acc[i][j] = fmaf(a[i], b[j], acc[i][j]);
        }
        __syncthreads();
    }

    const bool isq = (blockIdx.z == 0);
#pragma unroll
    for (int i = 0; i < 8; i++) {
        int m = m0 + ty * 8 + i;
        int bb = m >> 10, t = m & 1023;
#pragma unroll
        for (int j4 = 0; j4 < 8; j4 += 4) {
            int n = n0 + tx * 8 + j4;
            int h = n >> 6, d = n & 63;
            float4 v;
            v.x = acc[i][j4 + 0];
            v.y = acc[i][j4 + 1];
            v.z = acc[i][j4 + 2];
            v.w = acc[i][j4 + 3];
            if (isq) {
                v.x = nan2num(v.x); v.y = nan2num(v.y);
                v.z = nan2num(v.z); v.w = nan2num(v.w);
            }
            *reinterpret_cast<float4*>(&dst[((bb * HH + h) * TT + t) * DD + d]) = v;
        }
    }
}

// ---------------------------------------------------------------------------
// Output GEMM: g_attn[4096x1024] @ Wo[1024x1024] -> out (row-major)
// ---------------------------------------------------------------------------
__global__ __launch_bounds__(256) void out_gemm_kernel(
    const float* __restrict__ Wo, float* __restrict__ out)
{
    __shared__ float As[8][128];
    __shared__ float Bs[8][128];

    const int tid = threadIdx.x;
    const int m0 = blockIdx.y * 128;
    const int n0 = blockIdx.x * 128;

    const int arow = tid >> 1, acol = (tid & 1) * 4;
    const int brow = tid >> 5, bcol = (tid & 31) * 4;
    const float* Ap = g_attn + (m0 + arow) * CCH + acol;
    const float* Bp = Wo + brow * CCH + n0 + bcol;

    float acc[8][8];
#pragma unroll
    for (int i = 0; i < 8; i++)
#pragma unroll
        for (int j = 0; j < 8; j++) acc[i][j] = 0.f;

    const int ty = tid >> 4, tx = tid & 15;

#pragma unroll 1
    for (int kt = 0; kt < CCH; kt += 8) {
        float4 av = ld4(Ap + kt);
        float4 bv = ld4(Bp + kt * CCH);
        As[acol + 0][arow] = av.x;
        As[acol + 1][arow] = av.y;
        As[acol + 2][arow] = av.z;
        As[acol + 3][arow] = av.w;
        *reinterpret_cast<float4*>(&Bs[brow][bcol]) = bv;
        __syncthreads();
#pragma unroll
        for (int k = 0; k < 8; k++) {
            float a[8], b[8];
            *(float4*)&a[0] = *(const float4*)&As[k][ty * 8];
            *(float4*)&a[4] = *(const float4*)&As[k][ty * 8 + 4];
            *(float4*)&b[0] = *(const float4*)&Bs[k][tx * 8];
            *(float4*)&b[4] = *(const float4*)&Bs[k][tx * 8 + 4];
#pragma unroll
            for (int i = 0; i < 8; i++)
#pragma unroll
                for (int j = 0; j < 8; j++)
                    acc[i][j] = fmaf(a[i], b[j], acc[i][j]);
        }
        __syncthreads();
    }

#pragma unroll
    for (int i = 0; i < 8; i++) {
        int m = m0 + ty * 8 + i;
#pragma unroll
        for (int j4 = 0; j4 < 8; j4 += 4) {
            int n = n0 + tx * 8 + j4;
            float4 v;
            v.x = acc[i][j4 + 0];
            v.y = acc[i][j4 + 1];
            v.z = acc[i][j4 + 2];
            v.w = acc[i][j4 + 3];
            *reinterpret_cast<float4*>(&out[m * CCH + n]) = v;
        }
    }
}

// ---------------------------------------------------------------------------
// Attention: one block = (b, h, 64-query tile). 256 threads, 8 warps.
// Per chunk (16 chunks of 64 keys): S = Q K^T (scaled), per-row top-32
// threshold (bitonic sort of 64 across a warp), per-chunk softmax, O += P V.
// ---------------------------------------------------------------------------
__global__ __launch_bounds__(256) void attn_kernel(
    const float* __restrict__ imp, const float* __restrict__ temps)
{
    extern __shared__ float sm[];
    float (*QsT)[68] = reinterpret_cast<float(*)[68]>(sm);              // [d][q]
    float (*KsT)[68] = QsT + 64;                                        // [d][key]
    float (*Vs)[64] = reinterpret_cast<float(*)[64]>(sm + 2 * 64 * 68); // [key][d]
    float (*Ss)[64] = Vs + 64;                                          // [q][key]
    float* mw = sm + 2 * 64 * 68 + 2 * 64 * 64;                         // [64]
    float* psum = mw + 64;                                              // [64]

    const int qt = blockIdx.x, h = blockIdx.y, b = blockIdx.z;
    const int tid = threadIdx.x;
    const int lane = tid & 31, w = tid >> 5;
    const int ty = tid >> 4, tx = tid & 15;
    const int R = ty * 4;   // 4 query rows
    const int Cc = tx * 4;  // 4 key cols (phase A) / 4 dims (phase C)

    // Load Q tile transposed
    const float* qb = g_q + ((b * HH + h) * TT + qt * 64) * DD;
    for (int i = tid; i < 1024; i += 256) {
        int key = i >> 4;
        int dc = (i & 15) << 2;
        float4 qv = ld4(qb + key * 64 + dc);
        QsT[dc + 0][key] = qv.x;
        QsT[dc + 1][key] = qv.y;
        QsT[dc + 2][key] = qv.z;
        QsT[dc + 3][key] = qv.w;
    }
    if (tid < 64) {
        float tv = temps[b * HH + h];
        tv = fminf(fmaxf(tv, 0.1f), 100.f);
        float iv = imp[(b * TT + qt * 64 + tid) * HH + h];
        float s1 = 1.f / (1.f + expf(-iv));
        float mwv = 1.f / (1.f + expf(-(s1 - 0.5f) * 10.f));
        mw[tid] = mwv * (SCALE_F / tv);
        psum[tid] = 0.f;
    }

    float O[4][4];
#pragma unroll
    for (int i = 0; i < 4; i++)
#pragma unroll
        for (int j = 0; j < 4; j++) O[i][j] = 0.f;

#pragma unroll 1
    for (int kc = 0; kc < NKC; kc++) {
        const float* kb = g_k + ((b * HH + h) * TT + kc * 64) * DD;
        const float* vb = g_v + ((b * HH + h) * TT + kc * 64) * DD;
        __syncthreads();  // prev phase C done (and Q load on first iter)
        for (int i = tid; i < 1024; i += 256) {
            int key = i >> 4;
            int dc = (i & 15) << 2;
            float4 kv = ld4(kb + key * 64 + dc);
            KsT[dc + 0][key] = kv.x;
            KsT[dc + 1][key] = kv.y;
            KsT[dc + 2][key] = kv.z;
            KsT[dc + 3][key] = kv.w;
            float4 vv = ld4(vb + key * 64 + dc);
            *(float4*)&Vs[key][dc] = vv;
        }
        __syncthreads();

        // ---- Phase A: S[R..R+3][Cc..Cc+3] = Q K^T (outer product over d)
        float acc[4][4];
#pragma unroll
        for (int i = 0; i < 4; i++)
#pragma unroll
            for (int j = 0; j < 4; j++) acc[i][j] = 0.f;
#pragma unroll 16
        for (int d = 0; d < 64; d++) {
            float4 qv = *(const float4*)&QsT[d][R];
            float4 kv = *(const float4*)&KsT[d][Cc];
            acc[0][0] = fmaf(qv.x, kv.x, acc[0][0]);
            acc[0][1] = fmaf(qv.x, kv.y, acc[0][1]);
            acc[0][2] = fmaf(qv.x, kv.z, acc[0][2]);
            acc[0][3] = fmaf(qv.x, kv.w, acc[0][3]);
            acc[1][0] = fmaf(qv.y, kv.x, acc[1][0]);
            acc[1][1] = fmaf(qv.y, kv.y, acc[1][1]);
            acc[1][2] = fmaf(qv.y, kv.z, acc[1][2]);
            acc[1][3] = fmaf(qv.y, kv.w, acc[1][3]);
            acc[2][0] = fmaf(qv.z, kv.x, acc[2][0]);
            acc[2][1] = fmaf(qv.z, kv.y, acc[2][1]);
            acc[2][2] = fmaf(qv.z, kv.z, acc[2][2]);
            acc[2][3] = fmaf(qv.z, kv.w, acc[2][3]);
            acc[3][0] = fmaf(qv.w, kv.x, acc[3][0]);
            acc[3][1] = fmaf(qv.w, kv.y, acc[3][1]);
            acc[3][2] = fmaf(qv.w, kv.z, acc[3][2]);
            acc[3][3] = fmaf(qv.w, kv.w, acc[3][3]);
        }
#pragma unroll
        for (int i = 0; i < 4; i++) {
            float s = mw[R + i];
            float4 sv;
            sv.x = acc[i][0] * s;
            sv.y = acc[i][1] * s;
            sv.z = acc[i][2] * s;
            sv.w = acc[i][3] * s;
            *(float4*)&Ss[R + i][Cc] = sv;
        }
        __syncthreads();

        // ---- Phase B: per-row top-32 threshold + softmax. Warp w: rows w*8..w*8+7
#pragma unroll 1
        for (int rr = 0; rr < 8; rr++) {
            int row = w * 8 + rr;
            float s0 = Ss[row][lane];
            float s1 = Ss[row][lane + 32];

            // Bitonic sort 64 values ascending (2 regs/lane, element i = lane + 32r)
            float a0 = s0, a1 = s1;
#pragma unroll
            for (int size = 2; size <= 64; size <<= 1) {
#pragma unroll
                for (int stride = size >> 1; stride > 0; stride >>= 1) {
                    if (stride == 32) {
                        float lo = fminf(a0, a1), hi = fmaxf(a0, a1);
                        a0 = lo;
                        a1 = hi;
                    } else {
                        {
                            int i0 = lane;
                            bool asc = ((i0 & size) == 0);
                            float other = __shfl_xor_sync(0xffffffffu, a0, stride);
                            bool lower = ((i0 & stride) == 0);
                            a0 = (lower == asc) ? fminf(a0, other) : fmaxf(a0, other);
                        }
                        {
                            int i1 = lane + 32;
                            bool asc = ((i1 & size) == 0);
                            float other = __shfl_xor_sync(0xffffffffu, a1, stride);
                            bool lower = ((i1 & stride) == 0);
                            a1 = (lower == asc) ? fminf(a1, other) : fmaxf(a1, other);
                        }
                    }
                }
            }
            // sorted ascending: index 32 = 32nd largest = threshold
            float thr = __shfl_sync(0xffffffffu, a1, 0);

            float m0 = (s0 >= thr) ? s0 : 0.f;
            float m1 = (s1 >= thr) ? s1 : 0.f;
            float mx = fmaxf(m0, m1);
#pragma unroll
            for (int o = 16; o; o >>= 1)
                mx = fmaxf(mx, __shfl_xor_sync(0xffffffffu, mx, o));
            float e0 = expf(m0 - mx);
            float e1 = expf(m1 - mx);
            float sum = e0 + e1;
#pragma unroll
            for (int o = 16; o; o >>= 1)
                sum += __shfl_xor_sync(0xffffffffu, sum, o);
            float denom = fmaxf(sum, 1e-6f);
            float inv = 1.f / denom;
            Ss[row][lane] = e0 * inv;
            Ss[row][lane + 32] = e1 * inv;
            if (lane == 0) psum[row] += sum * inv;
        }
        __syncthreads();

        // ---- Phase C: O[R..R+3][Cc..Cc+3] += P V
#pragma unroll 4
        for (int c4 = 0; c4 < 64; c4 += 4) {
            float p[4][4];
#pragma unroll
            for (int i = 0; i < 4; i++) {
                float4 t4 = *(const float4*)&Ss[R + i][c4];
                p[i][0] = t4.x; p[i][1] = t4.y; p[i][2] = t4.z; p[i][3] = t4.w;
            }
            float v[4][4];
#pragma unroll
            for (int c = 0; c < 4; c++) {
                float4 t4 = *(const float4*)&Vs[c4 + c][Cc];
                v[c][0] = t4.x; v[c][1] = t4.y; v[c][2] = t4.z; v[c][3] = t4.w;
            }
#pragma unroll
            for (int i = 0; i < 4; i++)
#pragma unroll
                for (int c = 0; c < 4; c++)
#pragma unroll
                    for (int dd = 0; dd < 4; dd++)
                        O[i][dd] = fmaf(p[i][c], v[c][dd], O[i][dd]);
        }
    }

    // Epilogue: divide by normalizer, nan_to_num, store to g_attn [B][T][C]
#pragma unroll
    for (int i = 0; i < 4; i++) {
        int row = R + i;
        float nrm = fmaxf(psum[row], 1e-6f);
        float inv = 1.f / nrm;
        float4 o;
        o.x = nan2num(O[i][0] * inv);
        o.y = nan2num(O[i][1] * inv);
        o.z = nan2num(O[i][2] * inv);
        o.w = nan2num(O[i][3] * inv);
        int t = qt * 64 + row;
        *(float4*)&g_attn[(b * TT + t) * CCH + h * 64 + Cc] = o;
    }
}

// ---------------------------------------------------------------------------
extern "C" void kernel_launch(void* const* d_in, const int* in_sizes, int n_in,
                              void* d_out, int out_size)
{
    const float* x     = (const float*)d_in[0];
    const float* imp   = (const float*)d_in[1];
    const float* temps = (const float*)d_in[2];
    const float* Wq    = (const float*)d_in[3];
    const float* Wk    = (const float*)d_in[4];
    const float* Wv    = (const float*)d_in[5];
    const float* Wo    = (const float*)d_in[6];
    float* out = (float*)d_out;

    constexpr int smem_attn = (2 * 64 * 68 + 2 * 64 * 64 + 128) * 4;  // 68096 B
    cudaFuncSetAttribute(attn_kernel,
                         cudaFuncAttributeMaxDynamicSharedMemorySize, smem_attn);

    proj_kernel<<<dim3(8, 32, 3), 256>>>(x, Wq, Wk, Wv);
    attn_kernel<<<dim3(16, 16, 4), 256, smem_attn>>>(imp, temps);
    out_gemm_kernel<<<dim3(8, 32), 256>>>(Wo, out);
}

// round 3
// speedup vs baseline: 1.0245x; 1.0245x over previous
#include <cuda_runtime.h>
#include <math.h>

#define BB 4
#define TT 1024
#define CCH 1024
#define HH 16
#define DD 64
#define NKC 16
#define SCALE_F 0.125f

typedef unsigned long long ull;

// Scratch (device globals: allocation-free rule)
__device__ float g_q[BB * HH * TT * DD];
__device__ float g_k[BB * HH * TT * DD];
__device__ float g_v[BB * HH * TT * DD];
__device__ float g_attn[BB * TT * CCH];

__device__ __forceinline__ float4 ld4(const float* p) {
    return *reinterpret_cast<const float4*>(p);
}

__device__ __forceinline__ float nan2num(float v) {
    if (isnan(v)) return 0.f;
    if (isinf(v)) return v > 0.f ? 1.f : -1.f;
    return v;
}

// Packed f32x2 FMA: d += a * b (per 32-bit lane), full fp32 semantics.
#define FFMA2(d, a, b) \
    asm("fma.rn.f32x2 %0, %1, %2, %0;" : "+l"(d) : "l"(a), "l"(b))

__device__ __forceinline__ ull pack2(float x) {
    ull r;
    unsigned xi = __float_as_uint(x);
    asm("mov.b64 %0, {%1, %1};" : "=l"(r) : "r"(xi));
    return r;
}

__device__ __forceinline__ float2 unpk(ull v) {
    unsigned lo, hi;
    asm("mov.b64 {%0, %1}, %2;" : "=r"(lo), "=r"(hi) : "l"(v));
    return make_float2(__uint_as_float(lo), __uint_as_float(hi));
}

// ---------------------------------------------------------------------------
// SGEMM 128x128x8, 256 threads, 8x8 per thread via f32x2 packed FMA.
// A tile stored DUPLICATED in smem ((a,a) pairs) so no pack instructions in
// the inner loop. Double-buffered smem with LDG prefetch (1 sync / k-tile).
// ---------------------------------------------------------------------------
struct GemmCore {
    float As2[2][8][258];   // duplicated A: index 2*m holds (a,a)
    float Bs[2][8][128];
};

__device__ __forceinline__ void gemm_body(
    GemmCore* sh, const float* Ap, const float* Bp,
    ull acc[8][4], int ty, int tx,
    int arow, int acol, int brow, int bcol)
{
    float4 av = ld4(Ap);
    float4 bv = ld4(Bp);
    {
        *(float2*)&sh->As2[0][acol + 0][2 * arow] = make_float2(av.x, av.x);
        *(float2*)&sh->As2[0][acol + 1][2 * arow] = make_float2(av.y, av.y);
        *(float2*)&sh->As2[0][acol + 2][2 * arow] = make_float2(av.z, av.z);
        *(float2*)&sh->As2[0][acol + 3][2 * arow] = make_float2(av.w, av.w);
        *(float4*)&sh->Bs[0][brow][bcol] = bv;
    }
    __syncthreads();

#pragma unroll 1
    for (int kt = 0; kt < 128; kt++) {
        const int cur = kt & 1;
        if (kt < 127) {
            av = ld4(Ap + (kt + 1) * 8);
            bv = ld4(Bp + (kt + 1) * 8 * CCH);
        }
#pragma unroll
        for (int k = 0; k < 8; k++) {
            ull a2[8], b2[4];
            const ull* ap = (const ull*)&sh->As2[cur][k][ty * 16];
#pragma unroll
            for (int i = 0; i < 8; i++) a2[i] = ap[i];
            const ull* bp2 = (const ull*)&sh->Bs[cur][k][tx * 8];
#pragma unroll
            for (int j = 0; j < 4; j++) b2[j] = bp2[j];
#pragma unroll
            for (int i = 0; i < 8; i++)
#pragma unroll
                for (int j = 0; j < 4; j++)
                    FFMA2(acc[i][j], a2[i], b2[j]);
        }
        if (kt < 127) {
            const int nxt = cur ^ 1;
            *(float2*)&sh->As2[nxt][acol + 0][2 * arow] = make_float2(av.x, av.x);
            *(float2*)&sh->As2[nxt][acol + 1][2 * arow] = make_float2(av.y, av.y);
            *(float2*)&sh->As2[nxt][acol + 2][2 * arow] = make_float2(av.z, av.z);
            *(float2*)&sh->As2[nxt][acol + 3][2 * arow] = make_float2(av.w, av.w);
            *(float4*)&sh->Bs[nxt][brow][bcol] = bv;
            __syncthreads();
        }
    }
}

__global__ __launch_bounds__(256, 2) void proj_kernel(
    const float* __restrict__ x,
    const float* __restrict__ Wq,
    const float* __restrict__ Wk,
    const float* __restrict__ Wv)
{
    __shared__ GemmCore sh;

    const int tid = threadIdx.x;
    const int m0 = blockIdx.y * 128;
    const int n0 = blockIdx.x * 128;
    const float* W = (blockIdx.z == 0) ? Wq : (blockIdx.z == 1) ? Wk : Wv;
    float* dst     = (blockIdx.z == 0) ? g_q : (blockIdx.z == 1) ? g_k : g_v;

    const int arow = tid >> 1, acol = (tid & 1) * 4;
    const int brow = tid >> 5, bcol = (tid & 31) * 4;
    const int ty = tid >> 4, tx = tid & 15;

    ull acc[8][4];
#pragma unroll
    for (int i = 0; i < 8; i++)
#pragma unroll
        for (int j = 0; j < 4; j++) acc[i][j] = 0ull;

    gemm_body(&sh, x + (m0 + arow) * CCH + acol, W + brow * CCH + n0 + bcol,
              acc, ty, tx, arow, acol, brow, bcol);

    const bool isq = (blockIdx.z == 0);
#pragma unroll
    for (int i = 0; i < 8; i++) {
        int m = m0 + ty * 8 + i;
        int bb = m >> 10, t = m & 1023;
        float c[8];
#pragma unroll
        for (int j = 0; j < 4; j++) {
            float2 f = unpk(acc[i][j]);
            c[2 * j] = f.x;
            c[2 * j + 1] = f.y;
        }
#pragma unroll
        for (int j4 = 0; j4 < 8; j4 += 4) {
            int n = n0 + tx * 8 + j4;
            int h = n >> 6, d = n & 63;
            float4 v;
            v.x = c[j4 + 0]; v.y = c[j4 + 1]; v.z = c[j4 + 2]; v.w = c[j4 + 3];
            if (isq) {
                v.x = nan2num(v.x); v.y = nan2num(v.y);
                v.z = nan2num(v.z); v.w = nan2num(v.w);
            }
            *reinterpret_cast<float4*>(&dst[((bb * HH + h) * TT + t) * DD + d]) = v;
        }
    }
}

__global__ __launch_bounds__(256, 2) void out_gemm_kernel(
    const float* __restrict__ Wo, float* __restrict__ out)
{
    __shared__ GemmCore sh;

    const int tid = threadIdx.x;
    const int m0 = blockIdx.y * 128;
    const int n0 = blockIdx.x * 128;

    const int arow = tid >> 1, acol = (tid & 1) * 4;
    const int brow = tid >> 5, bcol = (tid & 31) * 4;
    const int ty = tid >> 4, tx = tid & 15;

    ull acc[8][4];
#pragma unroll
    for (int i = 0; i < 8; i++)
#pragma unroll
        for (int j = 0; j < 4; j++) acc[i][j] = 0ull;

    gemm_body(&sh, g_attn + (m0 + arow) * CCH + acol, Wo + brow * CCH + n0 + bcol,
              acc, ty, tx, arow, acol, brow, bcol);

#pragma unroll
    for (int i = 0; i < 8; i++) {
        int m = m0 + ty * 8 + i;
        float c[8];
#pragma unroll
        for (int j = 0; j < 4; j++) {
            float2 f = unpk(acc[i][j]);
            c[2 * j] = f.x;
            c[2 * j + 1] = f.y;
        }
#pragma unroll
        for (int j4 = 0; j4 < 8; j4 += 4) {
            int n = n0 + tx * 8 + j4;
            float4 v;
            v.x = c[j4 + 0]; v.y = c[j4 + 1]; v.z = c[j4 + 2]; v.w = c[j4 + 3];
            *reinterpret_cast<float4*>(&out[m * CCH + n]) = v;
        }
    }
}

// ---------------------------------------------------------------------------
// Attention: one block = (b, h, 64-query tile). 256 threads, 8 warps.
// Phase A: S = QK^T via f32x2 (rows paired; K broadcast packed in regs).
// Phase B: per-row top-32 threshold via 4-row-interleaved bitonic sort
//          (hides shfl latency), fast __expf softmax.
// Phase C: O += P V via f32x2 (dims paired; P broadcast packed).
// ---------------------------------------------------------------------------
__global__ __launch_bounds__(256) void attn_kernel(
    const float* __restrict__ imp, const float* __restrict__ temps)
{
    extern __shared__ float sm[];
    float (*QsT)[68] = reinterpret_cast<float(*)[68]>(sm);               // [d][q]
    float (*KsT)[68] = QsT + 64;                                         // [d][key]
    float (*Vs)[68]  = KsT + 64;                                         // [key][d]
    float (*Ss)[68]  = Vs + 64;                                          // [q][key]
    float* mw   = sm + 4 * 64 * 68;                                      // [64]
    float* psum = mw + 64;                                               // [64]

    const int qt = blockIdx.x, h = blockIdx.y, b = blockIdx.z;
    const int tid = threadIdx.x;
    const int lane = tid & 31, w = tid >> 5;
    const int ty = tid >> 4, tx = tid & 15;
    const int R = ty * 4;   // 4 query rows
    const int Cc = tx * 4;  // 4 key cols (A) / 4 dims (C)
    const unsigned FULL = 0xffffffffu;

    // Load Q tile transposed
    const float* qb = g_q + ((b * HH + h) * TT + qt * 64) * DD;
    for (int i = tid; i < 1024; i += 256) {
        int key = i >> 4;
        int dc = (i & 15) << 2;
        float4 qv = ld4(qb + key * 64 + dc);
        QsT[dc + 0][key] = qv.x;
        QsT[dc + 1][key] = qv.y;
        QsT[dc + 2][key] = qv.z;
        QsT[dc + 3][key] = qv.w;
    }
    if (tid < 64) {
        float tv = temps[b * HH + h];
        tv = fminf(fmaxf(tv, 0.1f), 100.f);
        float iv = imp[(b * TT + qt * 64 + tid) * HH + h];
        float s1 = 1.f / (1.f + __expf(-iv));
        float mwv = 1.f / (1.f + __expf(-(s1 - 0.5f) * 10.f));
        mw[tid] = mwv * (SCALE_F / tv);
        psum[tid] = 0.f;
    }

    ull O2[4][2];
#pragma unroll
    for (int i = 0; i < 4; i++) { O2[i][0] = 0ull; O2[i][1] = 0ull; }

#pragma unroll 1
    for (int kc = 0; kc < NKC; kc++) {
        const float* kb = g_k + ((b * HH + h) * TT + kc * 64) * DD;
        const float* vb = g_v + ((b * HH + h) * TT + kc * 64) * DD;
        __syncthreads();  // prev phase C done (and Q/mw load on first iter)
        for (int i = tid; i < 1024; i += 256) {
            int key = i >> 4;
            int dc = (i & 15) << 2;
            float4 kv = ld4(kb + key * 64 + dc);
            KsT[dc + 0][key] = kv.x;
            KsT[dc + 1][key] = kv.y;
            KsT[dc + 2][key] = kv.z;
            KsT[dc + 3][key] = kv.w;
            float4 vv = ld4(vb + key * 64 + dc);
            *(float4*)&Vs[key][dc] = vv;
        }
        __syncthreads();

        // ---- Phase A: S = Q K^T, rows paired via f32x2
        ull acc2[2][4];
#pragma unroll
        for (int p = 0; p < 2; p++)
#pragma unroll
            for (int j = 0; j < 4; j++) acc2[p][j] = 0ull;
#pragma unroll 8
        for (int d = 0; d < 64; d++) {
            const ull* qp = (const ull*)&QsT[d][R];
            ull q01 = qp[0], q23 = qp[1];
            float4 kv = *(const float4*)&KsT[d][Cc];
            ull k0 = pack2(kv.x), k1 = pack2(kv.y);
            ull k2 = pack2(kv.z), k3 = pack2(kv.w);
            FFMA2(acc2[0][0], q01, k0);
            FFMA2(acc2[0][1], q01, k1);
            FFMA2(acc2[0][2], q01, k2);
            FFMA2(acc2[0][3], q01, k3);
            FFMA2(acc2[1][0], q23, k0);
            FFMA2(acc2[1][1], q23, k1);
            FFMA2(acc2[1][2], q23, k2);
            FFMA2(acc2[1][3], q23, k3);
        }
        float sc[4][4];
#pragma unroll
        for (int p = 0; p < 2; p++)
#pragma unroll
            for (int j = 0; j < 4; j++) {
                float2 f = unpk(acc2[p][j]);
                sc[2 * p][j] = f.x;
                sc[2 * p + 1][j] = f.y;
            }
#pragma unroll
        for (int i = 0; i < 4; i++) {
            float s = mw[R + i];
            float4 sv;
            sv.x = sc[i][0] * s;
            sv.y = sc[i][1] * s;
            sv.z = sc[i][2] * s;
            sv.w = sc[i][3] * s;
            *(float4*)&Ss[R + i][Cc] = sv;
        }
        __syncthreads();

        // ---- Phase B: 4-row-interleaved bitonic top-32 + softmax
#pragma unroll 1
        for (int g = 0; g < 2; g++) {
            const int row0 = w * 8 + g * 4;
            float s0[4], s1[4], a0[4], a1[4];
#pragma unroll
            for (int r = 0; r < 4; r++) {
                s0[r] = Ss[row0 + r][lane];
                s1[r] = Ss[row0 + r][lane + 32];
                a0[r] = s0[r];
                a1[r] = s1[r];
            }
#pragma unroll
            for (int size = 2; size <= 64; size <<= 1) {
#pragma unroll
                for (int stride = size >> 1; stride > 0; stride >>= 1) {
                    if (stride == 32) {
#pragma unroll
                        for (int r = 0; r < 4; r++) {
                            float lo = fminf(a0[r], a1[r]);
                            float hi = fmaxf(a0[r], a1[r]);
                            a0[r] = lo;
                            a1[r] = hi;
                        }
                    } else {
                        const bool asc0 = ((lane & size) == 0);
                        const bool asc1 = (((lane + 32) & size) == 0);
                        const bool low = ((lane & stride) == 0);
#pragma unroll
                        for (int r = 0; r < 4; r++) {
                            float o = __shfl_xor_sync(FULL, a0[r], stride);
                            a0[r] = (low == asc0) ? fminf(a0[r], o) : fmaxf(a0[r], o);
                        }
#pragma unroll
                        for (int r = 0; r < 4; r++) {
                            float o = __shfl_xor_sync(FULL, a1[r], stride);
                            a1[r] = (low == asc1) ? fminf(a1[r], o) : fmaxf(a1[r], o);
                        }
                    }
                }
            }
            // ascending sorted; element (lane=0, upper reg) = index 32 = 32nd largest
            float thr[4], m0[4], m1[4], mx[4];
#pragma unroll
            for (int r = 0; r < 4; r++) {
                thr[r] = __shfl_sync(FULL, a1[r], 0);
                m0[r] = (s0[r] >= thr[r]) ? s0[r] : 0.f;
                m1[r] = (s1[r] >= thr[r]) ? s1[r] : 0.f;
                mx[r] = fmaxf(m0[r], m1[r]);
            }
#pragma unroll
            for (int o = 16; o; o >>= 1)
#pragma unroll
                for (int r = 0; r < 4; r++)
                    mx[r] = fmaxf(mx[r], __shfl_xor_sync(FULL, mx[r], o));
            float e0[4], e1[4], sum[4];
#pragma unroll
            for (int r = 0; r < 4; r++) {
                e0[r] = __expf(m0[r] - mx[r]);
                e1[r] = __expf(m1[r] - mx[r]);
                sum[r] = e0[r] + e1[r];
            }
#pragma unroll
            for (int o = 16; o; o >>= 1)
#pragma unroll
                for (int r = 0; r < 4; r++)
                    sum[r] += __shfl_xor_sync(FULL, sum[r], o);
#pragma unroll
            for (int r = 0; r < 4; r++) {
                float denom = fmaxf(sum[r], 1e-6f);
                float inv = 1.f / denom;
                Ss[row0 + r][lane] = e0[r] * inv;
                Ss[row0 + r][lane + 32] = e1[r] * inv;
                if (lane == 0) psum[row0 + r] += sum[r] * inv;
            }
        }
        __syncthreads();

        // ---- Phase C: O += P V, dims paired via f32x2
#pragma unroll 4
        for (int c4 = 0; c4 < 64; c4 += 4) {
            float pv[4][4];
#pragma unroll
            for (int i = 0; i < 4; i++) {
                float4 t4 = *(const float4*)&Ss[R + i][c4];
                pv[i][0] = t4.x; pv[i][1] = t4.y; pv[i][2] = t4.z; pv[i][3] = t4.w;
            }
#pragma unroll
            for (int c = 0; c < 4; c++) {
                const ull* vp = (const ull*)&Vs[c4 + c][Cc];
                ull v01 = vp[0], v23 = vp[1];
#pragma unroll
                for (int i = 0; i < 4; i++) {
                    ull pp = pack2(pv[i][c]);
                    FFMA2(O2[i][0], pp, v01);
                    FFMA2(O2[i][1], pp, v23);
                }
            }
        }
    }

    // Epilogue: divide by normalizer, nan_to_num, store to g_attn [B][T][C]
#pragma unroll
    for (int i = 0; i < 4; i++) {
        int row = R + i;
        float nrm = fmaxf(psum[row], 1e-6f);
        float inv = 1.f / nrm;
        float2 o01 = unpk(O2[i][0]);
        float2 o23 = unpk(O2[i][1]);
        float4 o;
        o.x = nan2num(o01.x * inv);
        o.y = nan2num(o01.y * inv);
        o.z = nan2num(o23.x * inv);
        o.w = nan2num(o23.y * inv);
        int t = qt * 64 + row;
        *(float4*)&g_attn[(b * TT + t) * CCH + h * 64 + Cc] = o;
    }
}

// ---------------------------------------------------------------------------
extern "C" void kernel_launch(void* const* d_in, const int* in_sizes, int n_in,
                              void* d_out, int out_size)
{
    const float* x     = (const float*)d_in[0];
    const float* imp   = (const float*)d_in[1];
    const float* temps = (const float*)d_in[2];
    const float* Wq    = (const float*)d_in[3];
    const float* Wk    = (const float*)d_in[4];
    const float* Wv    = (const float*)d_in[5];
    const float* Wo    = (const float*)d_in[6];
    float* out = (float*)d_out;

    constexpr int smem_attn = (4 * 64 * 68 + 128) * 4;  // 70144 B
    cudaFuncSetAttribute(attn_kernel,
                         cudaFuncAttributeMaxDynamicSharedMemorySize, smem_attn);

    proj_kernel<<<dim3(8, 32, 3), 256>>>(x, Wq, Wk, Wv);
    attn_kernel<<<dim3(16, 16, 4), 256, smem_attn>>>(imp, temps);
    out_gemm_kernel<<<dim3(8, 32), 256>>>(Wo, out);
}

// round 6
// speedup vs baseline: 1.5790x; 1.5412x over previous
#include <cuda_runtime.h>
#include <cuda_bf16.h>
#include <math.h>
#include <stdint.h>

#define BB 4
#define TT 1024
#define CCH 1024
#define HH 16
#define DD 64
#define NKC 16
#define SCALE_F 0.125f

typedef unsigned long long ull;
typedef __nv_bfloat16 bf16;

// Scratch (device globals: allocation-free rule)
__device__ float g_q[BB * HH * TT * DD];
__device__ float g_k[BB * HH * TT * DD];
__device__ float g_v[BB * HH * TT * DD];
__device__ bf16 g_xh[BB * TT * CCH], g_xl[BB * TT * CCH];       // x split
__device__ bf16 g_wth[4 * CCH * CCH], g_wtl[4 * CCH * CCH];     // W^T split
__device__ bf16 g_ah[BB * TT * CCH], g_al[BB * TT * CCH];       // attn split

__device__ __forceinline__ float4 ld4(const float* p) {
    return *reinterpret_cast<const float4*>(p);
}

__device__ __forceinline__ float nan2num(float v) {
    if (isnan(v)) return 0.f;
    if (isinf(v)) return v > 0.f ? 1.f : -1.f;
    return v;
}

__device__ __forceinline__ uint32_t smem_u32(const void* p) {
    uint32_t a;
    asm("{ .reg .u64 t; cvta.to.shared.u64 t, %1; cvt.u32.u64 %0, t; }"
        : "=r"(a) : "l"(p));
    return a;
}

__device__ __forceinline__ void split_bf16(float v, bf16& h, bf16& l) {
    h = __float2bfloat16(v);
    l = __float2bfloat16(v - __bfloat162float(h));
}

// ---------------- mma.sync building blocks (arch-agnostic HMMA) ----------------
__device__ __forceinline__ void cpa16(uint32_t s, const void* g) {
    asm volatile("cp.async.cg.shared.global [%0], [%1], 16;" :: "r"(s), "l"(g));
}

__device__ __forceinline__ void ldsm4(uint32_t r[4], uint32_t a) {
    asm volatile("ldmatrix.sync.aligned.m8n8.x4.shared.b16 {%0,%1,%2,%3}, [%4];"
                 : "=r"(r[0]), "=r"(r[1]), "=r"(r[2]), "=r"(r[3]) : "r"(a));
}

__device__ __forceinline__ void mma16816(float c[4], const uint32_t a[4],
                                         uint32_t b0, uint32_t b1) {
    asm volatile(
        "mma.sync.aligned.m16n8k16.row.col.f32.bf16.bf16.f32 "
        "{%0,%1,%2,%3}, {%4,%5,%6,%7}, {%8,%9}, {%0,%1,%2,%3};"
        : "+f"(c[0]), "+f"(c[1]), "+f"(c[2]), "+f"(c[3])
        : "r"(a[0]), "r"(a[1]), "r"(a[2]), "r"(a[3]), "r"(b0), "r"(b1));
}

// ---------------- GEMM tiling constants ----------------
#define KT 32                   // k per stage (bf16 elems)
#define NKT 32                  // 1024 / 32
#define ROWB 80                 // padded smem row bytes (40 bf16)
#define TILE_B (128 * ROWB)     // 10240
#define STAGE_B (4 * TILE_B)    // Ah, Al, Bh, Bl
#define NSTAGE 4
#define SMEM_GEMM (NSTAGE * STAGE_B)   // 163840

__device__ __forceinline__ void stage_load(
    uint32_t sbase, int s,
    const bf16* __restrict__ Ah, const bf16* __restrict__ Al,
    const bf16* __restrict__ Bh, const bf16* __restrict__ Bl,
    int kt, int tid)
{
    uint32_t st = sbase + s * STAGE_B;
    const bf16* srcs[4] = {Ah, Al, Bh, Bl};
#pragma unroll
    for (int tI = 0; tI < 4; tI++) {
        const bf16* src = srcs[tI] + kt * KT;
        uint32_t dst = st + tI * TILE_B;
#pragma unroll
        for (int i = 0; i < 2; i++) {
            int c = tid + i * 256;
            int row = c >> 2, seg = c & 3;
            cpa16(dst + row * ROWB + seg * 16, src + row * CCH + seg * 8);
        }
    }
}

// 128x128 tile, acc[mf][nf][4] per thread. 256 threads = 2x4 warps of 64x32.
__device__ __forceinline__ void gemm_core(
    const bf16* __restrict__ Ah, const bf16* __restrict__ Al,
    const bf16* __restrict__ Bh, const bf16* __restrict__ Bl,
    uint32_t sbase, int tid, float acc[4][4][4])
{
#pragma unroll
    for (int i = 0; i < 4; i++)
#pragma unroll
        for (int j = 0; j < 4; j++)
#pragma unroll
            for (int r = 0; r < 4; r++) acc[i][j][r] = 0.f;

    const int lane = tid & 31, warp = tid >> 5;
    const int wm = warp >> 2, wn = warp & 3;

    stage_load(sbase, 0, Ah, Al, Bh, Bl, 0, tid);
    asm volatile("cp.async.commit_group;");
    stage_load(sbase, 1, Ah, Al, Bh, Bl, 1, tid);
    asm volatile("cp.async.commit_group;");
    stage_load(sbase, 2, Ah, Al, Bh, Bl, 2, tid);
    asm volatile("cp.async.commit_group;");

    // ldmatrix per-lane offsets.
    // A tiles (m16k16): rows 0-7/8-15 by lane>>3 bit0, k-halves by lane>>4.
    const uint32_t aoff = (uint32_t)((wm * 64 + ((lane >> 3) & 1) * 8 + (lane & 7)) * ROWB
                                     + ((lane >> 4) & 1) * 16);
    // B tiles (two n8k16 frags): n rows by lane>>4 bit, k-halves by lane>>3 bit.
    const uint32_t boff = (uint32_t)((wn * 32 + ((lane >> 4) & 1) * 8 + (lane & 7)) * ROWB
                                     + ((lane >> 3) & 1) * 16);

#pragma unroll 1
    for (int c = 0; c < NKT; c++) {
        if (c < 30)       asm volatile("cp.async.wait_group 2;");
        else if (c == 30) asm volatile("cp.async.wait_group 1;");
        else              asm volatile("cp.async.wait_group 0;");
        __syncthreads();
        if (c + 3 < NKT) {
            stage_load(sbase, (c + 3) & 3, Ah, Al, Bh, Bl, c + 3, tid);
            asm volatile("cp.async.commit_group;");
        }
        const uint32_t st = sbase + (c & 3) * STAGE_B;
        const uint32_t aH = st + aoff;
        const uint32_t aL = st + TILE_B + aoff;
        const uint32_t bH = st + 2 * TILE_B + boff;
        const uint32_t bL = st + 3 * TILE_B + boff;
#pragma unroll
        for (int ks = 0; ks < 2; ks++) {
            const uint32_t kc = ks * 32;
            uint32_t ah[4][4], al[4][4], bh[2][4], bl[2][4];
#pragma unroll
            for (int mf = 0; mf < 4; mf++) {
                ldsm4(ah[mf], aH + mf * 16 * ROWB + kc);
                ldsm4(al[mf], aL + mf * 16 * ROWB + kc);
            }
#pragma unroll
            for (int p = 0; p < 2; p++) {
                ldsm4(bh[p], bH + p * 16 * ROWB + kc);
                ldsm4(bl[p], bL + p * 16 * ROWB + kc);
            }
#pragma unroll
            for (int mf = 0; mf < 4; mf++)
#pragma unroll
                for (int p = 0; p < 2; p++) {
                    mma16816(acc[mf][2 * p], ah[mf], bh[p][0], bh[p][1]);
                    mma16816(acc[mf][2 * p], ah[mf], bl[p][0], bl[p][1]);
                    mma16816(acc[mf][2 * p], al[mf], bh[p][0], bh[p][1]);
                    mma16816(acc[mf][2 * p + 1], ah[mf], bh[p][2], bh[p][3]);
                    mma16816(acc[mf][2 * p + 1], ah[mf], bl[p][2], bl[p][3]);
                    mma16816(acc[mf][2 * p + 1], al[mf], bh[p][2], bh[p][3]);
                }
        }
    }
}

// ---------------------------------------------------------------------------
// Prep: x -> bf16 hi/lo split
// ---------------------------------------------------------------------------
__global__ __launch_bounds__(256) void convx_kernel(const float* __restrict__ x)
{
    int i = blockIdx.x * 256 + threadIdx.x;   // one float4 each
    float4 v = ld4(x + i * 4);
    bf16 h0, h1, h2, h3, l0, l1, l2, l3;
    split_bf16(v.x, h0, l0);
    split_bf16(v.y, h1, l1);
    split_bf16(v.z, h2, l2);
    split_bf16(v.w, h3, l3);
    __nv_bfloat162 a, b;
    a.x = h0; a.y = h1; b.x = h2; b.y = h3;
    *(__nv_bfloat162*)&g_xh[i * 4] = a;
    *(__nv_bfloat162*)&g_xh[i * 4 + 2] = b;
    a.x = l0; a.y = l1; b.x = l2; b.y = l3;
    *(__nv_bfloat162*)&g_xl[i * 4] = a;
    *(__nv_bfloat162*)&g_xl[i * 4 + 2] = b;
}

// ---------------------------------------------------------------------------
// Prep: W[k][n] -> W^T[n][k] bf16 hi/lo, 4 matrices
// ---------------------------------------------------------------------------
__global__ __launch_bounds__(256) void transw_kernel(
    const float* __restrict__ Wq, const float* __restrict__ Wk,
    const float* __restrict__ Wv, const float* __restrict__ Wo)
{
    __shared__ float tile[32][33];
    const int z = blockIdx.z;
    const float* src = (z == 0) ? Wq : (z == 1) ? Wk : (z == 2) ? Wv : Wo;

    int tx = threadIdx.x & 31, ty = threadIdx.x >> 5;  // 32x8
    int x = blockIdx.x * 32 + tx;
    int y = blockIdx.y * 32 + ty;
#pragma unroll
    for (int j = 0; j < 32; j += 8)
        tile[ty + j][tx] = src[(y + j) * CCH + x];
    __syncthreads();
    int x2 = blockIdx.y * 32 + tx;
    int y2 = blockIdx.x * 32 + ty;
#pragma unroll
    for (int j = 0; j < 32; j += 8) {
        float v = tile[tx][ty + j];
        bf16 h, l;
        split_bf16(v, h, l);
        int idx = z * CCH * CCH + (y2 + j) * CCH + x2;
        g_wth[idx] = h;
        g_wtl[idx] = l;
    }
}

// ---------------------------------------------------------------------------
// Projection GEMM: q/k/v = x @ W{q,k,v}, dst fp32 [B][H][T][D]
// ---------------------------------------------------------------------------
__global__ __launch_bounds__(256) void proj_tc_kernel()
{
    extern __shared__ char smem[];
    const int tid = threadIdx.x;
    const int m0 = blockIdx.y * 128;
    const int n0 = blockIdx.x * 128;
    const int z = blockIdx.z;

    const bf16* Ah = g_xh + m0 * CCH;
    const bf16* Al = g_xl + m0 * CCH;
    const bf16* Bh = g_wth + z * CCH * CCH + n0 * CCH;
    const bf16* Bl = g_wtl + z * CCH * CCH + n0 * CCH;
    float* dst = (z == 0) ? g_q : (z == 1) ? g_k : g_v;

    float acc[4][4][4];
    gemm_core(Ah, Al, Bh, Bl, smem_u32(smem), tid, acc);

    const int lane = tid & 31, warp = tid >> 5;
    const int wm = warp >> 2, wn = warp & 3;
    const int g = lane >> 2, t4 = lane & 3;
    const bool isq = (z == 0);
#pragma unroll
    for (int mf = 0; mf < 4; mf++)
#pragma unroll
        for (int nf = 0; nf < 4; nf++)
#pragma unroll
            for (int rr = 0; rr < 2; rr++) {
                int m = m0 + wm * 64 + mf * 16 + g + rr * 8;
                int n = n0 + wn * 32 + nf * 8 + t4 * 2;
                int bb = m >> 10, tt = m & 1023;
                int hh = n >> 6, dd = n & 63;
                float2 v;
                v.x = acc[mf][nf][rr * 2];
                v.y = acc[mf][nf][rr * 2 + 1];
                if (isq) { v.x = nan2num(v.x); v.y = nan2num(v.y); }
                *(float2*)&dst[((bb * HH + hh) * TT + tt) * DD + dd] = v;
            }
}

// ---------------------------------------------------------------------------
// Output GEMM: out = attn @ Wo (attn already split bf16 by attention epilogue)
// ---------------------------------------------------------------------------
__global__ __launch_bounds__(256) void out_tc_kernel(float* __restrict__ out)
{
    extern __shared__ char smem[];
    const int tid = threadIdx.x;
    const int m0 = blockIdx.y * 128;
    const int n0 = blockIdx.x * 128;

    const bf16* Ah = g_ah + m0 * CCH;
    const bf16* Al = g_al + m0 * CCH;
    const bf16* Bh = g_wth + 3 * CCH * CCH + n0 * CCH;
    const bf16* Bl = g_wtl + 3 * CCH * CCH + n0 * CCH;

    float acc[4][4][4];
    gemm_core(Ah, Al, Bh, Bl, smem_u32(smem), tid, acc);

    const int lane = tid & 31, warp = tid >> 5;
    const int wm = warp >> 2, wn = warp & 3;
    const int g = lane >> 2, t4 = lane & 3;
#pragma unroll
    for (int mf = 0; mf < 4; mf++)
#pragma unroll
        for (int nf = 0; nf < 4; nf++)
#pragma unroll
            for (int rr = 0; rr < 2; rr++) {
                int m = m0 + wm * 64 + mf * 16 + g + rr * 8;
                int n = n0 + wn * 32 + nf * 8 + t4 * 2;
                float2 v;
                v.x = acc[mf][nf][rr * 2];
                v.y = acc[mf][nf][rr * 2 + 1];
                *(float2*)&out[m * CCH + n] = v;
            }
}

// ---------------------------------------------------------------------------
// Attention (R3 body): one block = (b, h, 64-query tile). 256 threads.
// Epilogue writes bf16 hi/lo split for the out-GEMM.
// ---------------------------------------------------------------------------
#define FFMA2(d, a, b) \
    asm("fma.rn.f32x2 %0, %1, %2, %0;" : "+l"(d) : "l"(a), "l"(b))

__device__ __forceinline__ ull pack2(float x) {
    ull r;
    unsigned xi = __float_as_uint(x);
    asm("mov.b64 %0, {%1, %1};" : "=l"(r) : "r"(xi));
    return r;
}

__device__ __forceinline__ float2 unpk(ull v) {
    unsigned lo, hi;
    asm("mov.b64 {%0, %1}, %2;" : "=r"(lo), "=r"(hi) : "l"(v));
    return make_float2(__uint_as_float(lo), __uint_as_float(hi));
}

__global__ __launch_bounds__(256) void attn_kernel(
    const float* __restrict__ imp, const float* __restrict__ temps)
{
    extern __shared__ float sm[];
    float (*QsT)[68] = reinterpret_cast<float(*)[68]>(sm);               // [d][q]
    float (*KsT)[68] = QsT + 64;                                         // [d][key]
    float (*Vs)[68]  = KsT + 64;                                         // [key][d]
    float (*Ss)[68]  = Vs + 64;                                          // [q][key]
    float* mw   = sm + 4 * 64 * 68;                                      // [64]
    float* psum = mw + 64;                                               // [64]

    const int qt = blockIdx.x, h = blockIdx.y, b = blockIdx.z;
    const int tid = threadIdx.x;
    const int lane = tid & 31, w = tid >> 5;
    const int ty = tid >> 4, tx = tid & 15;
    const int R = ty * 4;
    const int Cc = tx * 4;
    const unsigned FULL = 0xffffffffu;

    const float* qb = g_q + ((b * HH + h) * TT + qt * 64) * DD;
    for (int i = tid; i < 1024; i += 256) {
        int key = i >> 4;
        int dc = (i & 15) << 2;
        float4 qv = ld4(qb + key * 64 + dc);
        QsT[dc + 0][key] = qv.x;
        QsT[dc + 1][key] = qv.y;
        QsT[dc + 2][key] = qv.z;
        QsT[dc + 3][key] = qv.w;
    }
    if (tid < 64) {
        float tv = temps[b * HH + h];
        tv = fminf(fmaxf(tv, 0.1f), 100.f);
        float iv = imp[(b * TT + qt * 64 + tid) * HH + h];
        float s1 = 1.f / (1.f + __expf(-iv));
        float mwv = 1.f / (1.f + __expf(-(s1 - 0.5f) * 10.f));
        mw[tid] = mwv * (SCALE_F / tv);
        psum[tid] = 0.f;
    }

    ull O2[4][2];
#pragma unroll
    for (int i = 0; i < 4; i++) { O2[i][0] = 0ull; O2[i][1] = 0ull; }

#pragma unroll 1
    for (int kc = 0; kc < NKC; kc++) {
        const float* kb = g_k + ((b * HH + h) * TT + kc * 64) * DD;
        const float* vb = g_v + ((b * HH + h) * TT + kc * 64) * DD;
        __syncthreads();
        for (int i = tid; i < 1024; i += 256) {
            int key = i >> 4;
            int dc = (i & 15) << 2;
            float4 kv = ld4(kb + key * 64 + dc);
            KsT[dc + 0][key] = kv.x;
            KsT[dc + 1][key] = kv.y;
            KsT[dc + 2][key] = kv.z;
            KsT[dc + 3][key] = kv.w;
            float4 vv = ld4(vb + key * 64 + dc);
            *(float4*)&Vs[key][dc] = vv;
        }
        __syncthreads();

        // Phase A: S = Q K^T
        ull acc2[2][4];
#pragma unroll
        for (int p = 0; p < 2; p++)
#pragma unroll
            for (int j = 0; j < 4; j++) acc2[p][j] = 0ull;
#pragma unroll 8
        for (int d = 0; d < 64; d++) {
            const ull* qp = (const ull*)&QsT[d][R];
            ull q01 = qp[0], q23 = qp[1];
            float4 kv = *(const float4*)&KsT[d][Cc];
            ull k0 = pack2(kv.x), k1 = pack2(kv.y);
            ull k2 = pack2(kv.z), k3 = pack2(kv.w);
            FFMA2(acc2[0][0], q01, k0);
            FFMA2(acc2[0][1], q01, k1);
            FFMA2(acc2[0][2], q01, k2);
            FFMA2(acc2[0][3], q01, k3);
            FFMA2(acc2[1][0], q23, k0);
            FFMA2(acc2[1][1], q23, k1);
            FFMA2(acc2[1][2], q23, k2);
            FFMA2(acc2[1][3], q23, k3);
        }
        float sc[4][4];
#pragma unroll
        for (int p = 0; p < 2; p++)
#pragma unroll
            for (int j = 0; j < 4; j++) {
                float2 f = unpk(acc2[p][j]);
                sc[2 * p][j] = f.x;
                sc[2 * p + 1][j] = f.y;
            }
#pragma unroll
        for (int i = 0; i < 4; i++) {
            float s = mw[R + i];
            float4 sv;
            sv.x = sc[i][0] * s;
            sv.y = sc[i][1] * s;
            sv.z = sc[i][2] * s;
            sv.w = sc[i][3] * s;
            *(float4*)&Ss[R + i][Cc] = sv;
        }
        __syncthreads();

        // Phase B: 4-row-interleaved bitonic top-32 + softmax
#pragma unroll 1
        for (int g = 0; g < 2; g++) {
            const int row0 = w * 8 + g * 4;
            float s0[4], s1[4], a0[4], a1[4];
#pragma unroll
            for (int r = 0; r < 4; r++) {
                s0[r] = Ss[row0 + r][lane];
                s1[r] = Ss[row0 + r][lane + 32];
                a0[r] = s0[r];
                a1[r] = s1[r];
            }
#pragma unroll
            for (int size = 2; size <= 64; size <<= 1) {
#pragma unroll
                for (int stride = size >> 1; stride > 0; stride >>= 1) {
                    if (stride == 32) {
#pragma unroll
                        for (int r = 0; r < 4; r++) {
                            float lo = fminf(a0[r], a1[r]);
                            float hi = fmaxf(a0[r], a1[r]);
                            a0[r] = lo;
                            a1[r] = hi;
                        }
                    } else {
                        const bool asc0 = ((lane & size) == 0);
                        const bool asc1 = (((lane + 32) & size) == 0);
                        const bool low = ((lane & stride) == 0);
#pragma unroll
                        for (int r = 0; r < 4; r++) {
                            float o = __shfl_xor_sync(FULL, a0[r], stride);
                            a0[r] = (low == asc0) ? fminf(a0[r], o) : fmaxf(a0[r], o);
                        }
#pragma unroll
                        for (int r = 0; r < 4; r++) {
                            float o = __shfl_xor_sync(FULL, a1[r], stride);
                            a1[r] = (low == asc1) ? fminf(a1[r], o) : fmaxf(a1[r], o);
                        }
                    }
                }
            }
            float thr[4], m0[4], m1[4], mx[4];
#pragma unroll
            for (int r = 0; r < 4; r++) {
                thr[r] = __shfl_sync(FULL, a1[r], 0);
                m0[r] = (s0[r] >= thr[r]) ? s0[r] : 0.f;
                m1[r] = (s1[r] >= thr[r]) ? s1[r] : 0.f;
                mx[r] = fmaxf(m0[r], m1[r]);
            }
#pragma unroll
            for (int o = 16; o; o >>= 1)
#pragma unroll
                for (int r = 0; r < 4; r++)
                    mx[r] = fmaxf(mx[r], __shfl_xor_sync(FULL, mx[r], o));
            float e0[4], e1[4], sum[4];
#pragma unroll
            for (int r = 0; r < 4; r++) {
                e0[r] = __expf(m0[r] - mx[r]);
                e1[r] = __expf(m1[r] - mx[r]);
                sum[r] = e0[r] + e1[r];
            }
#pragma unroll
            for (int o = 16; o; o >>= 1)
#pragma unroll
                for (int r = 0; r < 4; r++)
                    sum[r] += __shfl_xor_sync(FULL, sum[r], o);
#pragma unroll
            for (int r = 0; r < 4; r++) {
                float denom = fmaxf(sum[r], 1e-6f);
                float inv = 1.f / denom;
                Ss[row0 + r][lane] = e0[r] * inv;
                Ss[row0 + r][lane + 32] = e1[r] * inv;
                if (lane == 0) psum[row0 + r] += sum[r] * inv;
            }
        }
        __syncthreads();

        // Phase C: O += P V
#pragma unroll 4
        for (int c4 = 0; c4 < 64; c4 += 4) {
            float pv[4][4];
#pragma unroll
            for (int i = 0; i < 4; i++) {
                float4 t4 = *(const float4*)&Ss[R + i][c4];
                pv[i][0] = t4.x; pv[i][1] = t4.y; pv[i][2] = t4.z; pv[i][3] = t4.w;
            }
#pragma unroll
            for (int c = 0; c < 4; c++) {
                const ull* vp = (const ull*)&Vs[c4 + c][Cc];
                ull v01 = vp[0], v23 = vp[1];
#pragma unroll
                for (int i = 0; i < 4; i++) {
                    ull pp = pack2(pv[i][c]);
                    FFMA2(O2[i][0], pp, v01);
                    FFMA2(O2[i][1], pp, v23);
                }
            }
        }
    }

    // Epilogue: normalize, nan_to_num, split to bf16 hi/lo for out-GEMM
#pragma unroll
    for (int i = 0; i < 4; i++) {
        int row = R + i;
        float nrm = fmaxf(psum[row], 1e-6f);
        float inv = 1.f / nrm;
        float2 o01 = unpk(O2[i][0]);
        float2 o23 = unpk(O2[i][1]);
        float ov[4];
        ov[0] = nan2num(o01.x * inv);
        ov[1] = nan2num(o01.y * inv);
        ov[2] = nan2num(o23.x * inv);
        ov[3] = nan2num(o23.y * inv);
        int t = qt * 64 + row;
        int base = (b * TT + t) * CCH + h * 64 + Cc;
        bf16 hi[4], lo[4];
#pragma unroll
        for (int j = 0; j < 4; j++) split_bf16(ov[j], hi[j], lo[j]);
        __nv_bfloat162 p;
        p.x = hi[0]; p.y = hi[1];
        *(__nv_bfloat162*)&g_ah[base] = p;
        p.x = hi[2]; p.y = hi[3];
        *(__nv_bfloat162*)&g_ah[base + 2] = p;
        p.x = lo[0]; p.y = lo[1];
        *(__nv_bfloat162*)&g_al[base] = p;
        p.x = lo[2]; p.y = lo[3];
        *(__nv_bfloat162*)&g_al[base + 2] = p;
    }
}

// ---------------------------------------------------------------------------
extern "C" void kernel_launch(void* const* d_in, const int* in_sizes, int n_in,
                              void* d_out, int out_size)
{
    const float* x     = (const float*)d_in[0];
    const float* imp   = (const float*)d_in[1];
    const float* temps = (const float*)d_in[2];
    const float* Wq    = (const float*)d_in[3];
    const float* Wk    = (const float*)d_in[4];
    const float* Wv    = (const float*)d_in[5];
    const float* Wo    = (const float*)d_in[6];
    float* out = (float*)d_out;

    constexpr int smem_attn = (4 * 64 * 68 + 128) * 4;  // 70144 B
    cudaFuncSetAttribute(attn_kernel,
                         cudaFuncAttributeMaxDynamicSharedMemorySize, smem_attn);
    cudaFuncSetAttribute(proj_tc_kernel,
                         cudaFuncAttributeMaxDynamicSharedMemorySize, SMEM_GEMM);
    cudaFuncSetAttribute(out_tc_kernel,
                         cudaFuncAttributeMaxDynamicSharedMemorySize, SMEM_GEMM);

    convx_kernel<<<BB * TT * CCH / 1024, 256>>>(x);
    transw_kernel<<<dim3(32, 32, 4), 256>>>(Wq, Wk, Wv, Wo);
    proj_tc_kernel<<<dim3(8, 32, 3), 256, SMEM_GEMM>>>();
    attn_kernel<<<dim3(16, 16, 4), 256, smem_attn>>>(imp, temps);
    out_tc_kernel<<<dim3(8, 32), 256, SMEM_GEMM>>>(out);
}

// round 7
// speedup vs baseline: 2.0656x; 1.3082x over previous
#include <cuda_runtime.h>
#include <cuda_bf16.h>
#include <math.h>
#include <stdint.h>

#define BB 4
#define TT 1024
#define CCH 1024
#define HH 16
#define DD 64
#define NKC 16
#define SCALE_F 0.125f

typedef unsigned long long ull;
typedef __nv_bfloat16 bf16;

// Scratch (device globals: allocation-free rule)
__device__ bf16 g_qh[BB * HH * TT * DD], g_ql[BB * HH * TT * DD];
__device__ bf16 g_kh[BB * HH * TT * DD], g_kl[BB * HH * TT * DD];
__device__ bf16 g_vh[BB * HH * TT * DD], g_vl[BB * HH * TT * DD];
__device__ bf16 g_xh[BB * TT * CCH], g_xl[BB * TT * CCH];       // x split
__device__ bf16 g_wth[4 * CCH * CCH], g_wtl[4 * CCH * CCH];     // W^T split
__device__ bf16 g_ah[BB * TT * CCH], g_al[BB * TT * CCH];       // attn split

__device__ __forceinline__ float4 ld4(const float* p) {
    return *reinterpret_cast<const float4*>(p);
}

__device__ __forceinline__ float nan2num(float v) {
    if (isnan(v)) return 0.f;
    if (isinf(v)) return v > 0.f ? 1.f : -1.f;
    return v;
}

__device__ __forceinline__ uint32_t smem_u32(const void* p) {
    uint32_t a;
    asm("{ .reg .u64 t; cvta.to.shared.u64 t, %1; cvt.u32.u64 %0, t; }"
        : "=r"(a) : "l"(p));
    return a;
}

__device__ __forceinline__ void split_bf16(float v, bf16& h, bf16& l) {
    h = __float2bfloat16(v);
    l = __float2bfloat16(v - __bfloat162float(h));
}

__device__ __forceinline__ __nv_bfloat162 mkbf2(bf16 a, bf16 b) {
    __nv_bfloat162 r;
    r.x = a;
    r.y = b;
    return r;
}

// ---------------- mma.sync building blocks ----------------
__device__ __forceinline__ void cpa16(uint32_t s, const void* g) {
    asm volatile("cp.async.cg.shared.global [%0], [%1], 16;" :: "r"(s), "l"(g));
}
#define CP_COMMIT() asm volatile("cp.async.commit_group;")
#define CP_WAIT0() asm volatile("cp.async.wait_group 0;")
#define CP_WAIT1() asm volatile("cp.async.wait_group 1;")
#define CP_WAIT2() asm volatile("cp.async.wait_group 2;")

__device__ __forceinline__ void ldsm4(uint32_t r[4], uint32_t a) {
    asm volatile("ldmatrix.sync.aligned.m8n8.x4.shared.b16 {%0,%1,%2,%3}, [%4];"
                 : "=r"(r[0]), "=r"(r[1]), "=r"(r[2]), "=r"(r[3]) : "r"(a));
}

__device__ __forceinline__ void ldsm4t(uint32_t r[4], uint32_t a) {
    asm volatile("ldmatrix.sync.aligned.m8n8.x4.trans.shared.b16 {%0,%1,%2,%3}, [%4];"
                 : "=r"(r[0]), "=r"(r[1]), "=r"(r[2]), "=r"(r[3]) : "r"(a));
}

__device__ __forceinline__ void mma16816(float c[4], const uint32_t a[4],
                                         uint32_t b0, uint32_t b1) {
    asm volatile(
        "mma.sync.aligned.m16n8k16.row.col.f32.bf16.bf16.f32 "
        "{%0,%1,%2,%3}, {%4,%5,%6,%7}, {%8,%9}, {%0,%1,%2,%3};"
        : "+f"(c[0]), "+f"(c[1]), "+f"(c[2]), "+f"(c[3])
        : "r"(a[0]), "r"(a[1]), "r"(a[2]), "r"(a[3]), "r"(b0), "r"(b1));
}

// ---------------- dense GEMM tiling (R6, proven) ----------------
#define KT 32
#define NKT 32
#define ROWB 80
#define TILE_B (128 * ROWB)
#define STAGE_B (4 * TILE_B)
#define NSTAGE 4
#define SMEM_GEMM (NSTAGE * STAGE_B)

__device__ __forceinline__ void stage_load(
    uint32_t sbase, int s,
    const bf16* __restrict__ Ah, const bf16* __restrict__ Al,
    const bf16* __restrict__ Bh, const bf16* __restrict__ Bl,
    int kt, int tid)
{
    uint32_t st = sbase + s * STAGE_B;
    const bf16* srcs[4] = {Ah, Al, Bh, Bl};
#pragma unroll
    for (int tI = 0; tI < 4; tI++) {
        const bf16* src = srcs[tI] + kt * KT;
        uint32_t dst = st + tI * TILE_B;
#pragma unroll
        for (int i = 0; i < 2; i++) {
            int c = tid + i * 256;
            int row = c >> 2, seg = c & 3;
            cpa16(dst + row * ROWB + seg * 16, src + row * CCH + seg * 8);
        }
    }
}

__device__ __forceinline__ void gemm_core(
    const bf16* __restrict__ Ah, const bf16* __restrict__ Al,
    const bf16* __restrict__ Bh, const bf16* __restrict__ Bl,
    uint32_t sbase, int tid, float acc[4][4][4])
{
#pragma unroll
    for (int i = 0; i < 4; i++)
#pragma unroll
        for (int j = 0; j < 4; j++)
#pragma unroll
            for (int r = 0; r < 4; r++) acc[i][j][r] = 0.f;

    const int lane = tid & 31, warp = tid >> 5;
    const int wm = warp >> 2, wn = warp & 3;

    stage_load(sbase, 0, Ah, Al, Bh, Bl, 0, tid);
    CP_COMMIT();
    stage_load(sbase, 1, Ah, Al, Bh, Bl, 1, tid);
    CP_COMMIT();
    stage_load(sbase, 2, Ah, Al, Bh, Bl, 2, tid);
    CP_COMMIT();

    const uint32_t aoff = (uint32_t)((wm * 64 + ((lane >> 3) & 1) * 8 + (lane & 7)) * ROWB
                                     + ((lane >> 4) & 1) * 16);
    const uint32_t boff = (uint32_t)((wn * 32 + ((lane >> 4) & 1) * 8 + (lane & 7)) * ROWB
                                     + ((lane >> 3) & 1) * 16);

#pragma unroll 1
    for (int c = 0; c < NKT; c++) {
        if (c < 30)       CP_WAIT2();
        else if (c == 30) CP_WAIT1();
        else              CP_WAIT0();
        __syncthreads();
        if (c + 3 < NKT) {
            stage_load(sbase, (c + 3) & 3, Ah, Al, Bh, Bl, c + 3, tid);
            CP_COMMIT();
        }
        const uint32_t st = sbase + (c & 3) * STAGE_B;
        const uint32_t aH = st + aoff;
        const uint32_t aL = st + TILE_B + aoff;
        const uint32_t bH = st + 2 * TILE_B + boff;
        const uint32_t bL = st + 3 * TILE_B + boff;
#pragma unroll
        for (int ks = 0; ks < 2; ks++) {
            const uint32_t kc = ks * 32;
            uint32_t ah[4][4], al[4][4], bh[2][4], bl[2][4];
#pragma unroll
            for (int mf = 0; mf < 4; mf++) {
                ldsm4(ah[mf], aH + mf * 16 * ROWB + kc);
                ldsm4(al[mf], aL + mf * 16 * ROWB + kc);
            }
#pragma unroll
            for (int p = 0; p < 2; p++) {
                ldsm4(bh[p], bH + p * 16 * ROWB + kc);
                ldsm4(bl[p], bL + p * 16 * ROWB + kc);
            }
#pragma unroll
            for (int mf = 0; mf < 4; mf++)
#pragma unroll
                for (int p = 0; p < 2; p++) {
                    mma16816(acc[mf][2 * p], ah[mf], bh[p][0], bh[p][1]);
                    mma16816(acc[mf][2 * p], ah[mf], bl[p][0], bl[p][1]);
                    mma16816(acc[mf][2 * p], al[mf], bh[p][0], bh[p][1]);
                    mma16816(acc[mf][2 * p + 1], ah[mf], bh[p][2], bh[p][3]);
                    mma16816(acc[mf][2 * p + 1], ah[mf], bl[p][2], bl[p][3]);
                    mma16816(acc[mf][2 * p + 1], al[mf], bh[p][2], bh[p][3]);
                }
        }
    }
}

// ---------------------------------------------------------------------------
// Prep kernels
// ---------------------------------------------------------------------------
__global__ __launch_bounds__(256) void convx_kernel(const float* __restrict__ x)
{
    int i = blockIdx.x * 256 + threadIdx.x;
    float4 v = ld4(x + i * 4);
    bf16 h0, h1, h2, h3, l0, l1, l2, l3;
    split_bf16(v.x, h0, l0);
    split_bf16(v.y, h1, l1);
    split_bf16(v.z, h2, l2);
    split_bf16(v.w, h3, l3);
    *(__nv_bfloat162*)&g_xh[i * 4] = mkbf2(h0, h1);
    *(__nv_bfloat162*)&g_xh[i * 4 + 2] = mkbf2(h2, h3);
    *(__nv_bfloat162*)&g_xl[i * 4] = mkbf2(l0, l1);
    *(__nv_bfloat162*)&g_xl[i * 4 + 2] = mkbf2(l2, l3);
}

__global__ __launch_bounds__(256) void transw_kernel(
    const float* __restrict__ Wq, const float* __restrict__ Wk,
    const float* __restrict__ Wv, const float* __restrict__ Wo)
{
    __shared__ float tile[32][33];
    const int z = blockIdx.z;
    const float* src = (z == 0) ? Wq : (z == 1) ? Wk : (z == 2) ? Wv : Wo;

    int tx = threadIdx.x & 31, ty = threadIdx.x >> 5;
    int x = blockIdx.x * 32 + tx;
    int y = blockIdx.y * 32 + ty;
#pragma unroll
    for (int j = 0; j < 32; j += 8)
        tile[ty + j][tx] = src[(y + j) * CCH + x];
    __syncthreads();
    int x2 = blockIdx.y * 32 + tx;
    int y2 = blockIdx.x * 32 + ty;
#pragma unroll
    for (int j = 0; j < 32; j += 8) {
        float v = tile[tx][ty + j];
        bf16 h, l;
        split_bf16(v, h, l);
        int idx = z * CCH * CCH + (y2 + j) * CCH + x2;
        g_wth[idx] = h;
        g_wtl[idx] = l;
    }
}

// ---------------------------------------------------------------------------
// Projection GEMM: q/k/v = x @ W{q,k,v}, dst bf16 hi/lo [B][H][T][D]
// ---------------------------------------------------------------------------
__global__ __launch_bounds__(256) void proj_tc_kernel()
{
    extern __shared__ char smem[];
    const int tid = threadIdx.x;
    const int m0 = blockIdx.y * 128;
    const int n0 = blockIdx.x * 128;
    const int z = blockIdx.z;

    const bf16* Ah = g_xh + m0 * CCH;
    const bf16* Al = g_xl + m0 * CCH;
    const bf16* Bh = g_wth + z * CCH * CCH + n0 * CCH;
    const bf16* Bl = g_wtl + z * CCH * CCH + n0 * CCH;
    bf16* dsth = (z == 0) ? g_qh : (z == 1) ? g_kh : g_vh;
    bf16* dstl = (z == 0) ? g_ql : (z == 1) ? g_kl : g_vl;

    float acc[4][4][4];
    gemm_core(Ah, Al, Bh, Bl, smem_u32(smem), tid, acc);

    const int lane = tid & 31, warp = tid >> 5;
    const int wm = warp >> 2, wn = warp & 3;
    const int g = lane >> 2, t4 = lane & 3;
    const bool isq = (z == 0);
#pragma unroll
    for (int mf = 0; mf < 4; mf++)
#pragma unroll
        for (int nf = 0; nf < 4; nf++)
#pragma unroll
            for (int rr = 0; rr < 2; rr++) {
                int m = m0 + wm * 64 + mf * 16 + g + rr * 8;
                int n = n0 + wn * 32 + nf * 8 + t4 * 2;
                int bb = m >> 10, tt = m & 1023;
                int hh = n >> 6, dd = n & 63;
                float v0 = acc[mf][nf][rr * 2];
                float v1 = acc[mf][nf][rr * 2 + 1];
                if (isq) { v0 = nan2num(v0); v1 = nan2num(v1); }
                bf16 h0, h1, l0, l1;
                split_bf16(v0, h0, l0);
                split_bf16(v1, h1, l1);
                int idx = ((bb * HH + hh) * TT + tt) * DD + dd;
                *(__nv_bfloat162*)&dsth[idx] = mkbf2(h0, h1);
                *(__nv_bfloat162*)&dstl[idx] = mkbf2(l0, l1);
            }
}

// ---------------------------------------------------------------------------
// Output GEMM: out = attn @ Wo
// ---------------------------------------------------------------------------
__global__ __launch_bounds__(256) void out_tc_kernel(float* __restrict__ out)
{
    extern __shared__ char smem[];
    const int tid = threadIdx.x;
    const int m0 = blockIdx.y * 128;
    const int n0 = blockIdx.x * 128;

    const bf16* Ah = g_ah + m0 * CCH;
    const bf16* Al = g_al + m0 * CCH;
    const bf16* Bh = g_wth + 3 * CCH * CCH + n0 * CCH;
    const bf16* Bl = g_wtl + 3 * CCH * CCH + n0 * CCH;

    float acc[4][4][4];
    gemm_core(Ah, Al, Bh, Bl, smem_u32(smem), tid, acc);

    const int lane = tid & 31, warp = tid >> 5;
    const int wm = warp >> 2, wn = warp & 3;
    const int g = lane >> 2, t4 = lane & 3;
#pragma unroll
    for (int mf = 0; mf < 4; mf++)
#pragma unroll
        for (int nf = 0; nf < 4; nf++)
#pragma unroll
            for (int rr = 0; rr < 2; rr++) {
                int m = m0 + wm * 64 + mf * 16 + g + rr * 8;
                int n = n0 + wn * 32 + nf * 8 + t4 * 2;
                float2 v;
                v.x = acc[mf][nf][rr * 2];
                v.y = acc[mf][nf][rr * 2 + 1];
                *(float2*)&out[m * CCH + n] = v;
            }
}

// ---------------------------------------------------------------------------
// Tensor-core attention. CTA = (b, h, 128-query tile), 8 warps (4m x 2n).
// ---------------------------------------------------------------------------
#define QSTR 144
#define SSTR 272
#define AQH 0
#define AQL 18432
#define AKH 36864
#define AKL 46080
#define AVH 55296
#define AVL 64512
#define AS  73728
#define AMW 108544
#define APS 109056
#define SMEM_ATTN 109568

__device__ __forceinline__ void kv_issue(uint32_t dh, uint32_t dl,
                                         const bf16* sh, const bf16* sl, int tid)
{
#pragma unroll
    for (int i = 0; i < 2; i++) {
        int cix = tid + i * 256;
        int row = cix >> 3, seg = cix & 7;
        cpa16(dh + row * QSTR + seg * 16, sh + row * 64 + seg * 8);
        cpa16(dl + row * QSTR + seg * 16, sl + row * 64 + seg * 8);
    }
}

__global__ __launch_bounds__(256, 2) void attn_kernel(
    const float* __restrict__ imp, const float* __restrict__ temps)
{
    extern __shared__ char smc[];
    const uint32_t sb = smem_u32(smc);
    float* mwp = (float*)(smc + AMW);
    float* psp = (float*)(smc + APS);

    const int qt = blockIdx.x, h = blockIdx.y, b = blockIdx.z;
    const int tid = threadIdx.x;
    const int lane = tid & 31, warp = tid >> 5;
    const int wm = warp >> 1, wn = warp & 1;
    const int g = lane >> 2, t4 = lane & 3;
    const unsigned FULL = 0xffffffffu;

    const int hbase = ((b * HH + h) * TT) * DD;
    const int qb = hbase + qt * 128 * DD;

    // Preamble: Q + chunk-0 K/V loads
#pragma unroll
    for (int i = 0; i < 4; i++) {
        int cix = tid + i * 256;
        int row = cix >> 3, seg = cix & 7;
        cpa16(sb + AQH + row * QSTR + seg * 16, g_qh + qb + row * 64 + seg * 8);
        cpa16(sb + AQL + row * QSTR + seg * 16, g_ql + qb + row * 64 + seg * 8);
    }
    kv_issue(sb + AKH, sb + AKL, g_kh + hbase, g_kl + hbase, tid);
    kv_issue(sb + AVH, sb + AVL, g_vh + hbase, g_vl + hbase, tid);
    CP_COMMIT();

    if (tid < 128) {
        float tv = temps[b * HH + h];
        tv = fminf(fmaxf(tv, 0.1f), 100.f);
        float iv = imp[(b * TT + qt * 128 + tid) * HH + h];
        float s1 = 1.f / (1.f + __expf(-iv));
        float mwv = 1.f / (1.f + __expf(-(s1 - 0.5f) * 10.f));
        mwp[tid] = mwv * (SCALE_F / tv);
        psp[tid] = 0.f;
    }
    CP_WAIT0();
    __syncthreads();

    // ldmatrix lane offsets
    const uint32_t aoff = (uint32_t)((wm * 32 + ((lane >> 3) & 1) * 8 + (lane & 7)) * QSTR
                                     + ((lane >> 4) & 1) * 16);
    const uint32_t koff = (uint32_t)((wn * 32 + ((lane >> 4) & 1) * 8 + (lane & 7)) * QSTR
                                     + ((lane >> 3) & 1) * 16);
    const uint32_t poff = (uint32_t)((wm * 32 + ((lane >> 3) & 1) * 8 + (lane & 7)) * SSTR
                                     + ((lane >> 4) & 1) * 16);
    const uint32_t voff = (uint32_t)((((lane >> 3) & 1) * 8 + (lane & 7)) * QSTR
                                     + ((lane >> 4) & 1) * 16 + wn * 64);

    float O[2][4][4];
#pragma unroll
    for (int i = 0; i < 2; i++)
#pragma unroll
        for (int j = 0; j < 4; j++)
#pragma unroll
            for (int r = 0; r < 4; r++) O[i][j][r] = 0.f;

#pragma unroll 1
    for (int c = 0; c < NKC; c++) {
        if (c > 0) {
            CP_WAIT1();     // K(c) landed (V(c) may still fly)
            __syncthreads();
        }

        // ---- Phase A: S = Q K^T (3-term bf16), scaled, to smem fp32
        {
            float acc[2][4][4];
#pragma unroll
            for (int i = 0; i < 2; i++)
#pragma unroll
                for (int j = 0; j < 4; j++)
#pragma unroll
                    for (int r = 0; r < 4; r++) acc[i][j][r] = 0.f;
#pragma unroll
            for (int ks = 0; ks < 4; ks++) {
                uint32_t ah[2][4], al[2][4], bh[2][4], bl[2][4];
#pragma unroll
                for (int mf = 0; mf < 2; mf++) {
                    ldsm4(ah[mf], sb + AQH + aoff + mf * 16 * QSTR + ks * 32);
                    ldsm4(al[mf], sb + AQL + aoff + mf * 16 * QSTR + ks * 32);
                }
#pragma unroll
                for (int nf = 0; nf < 2; nf++) {
                    ldsm4(bh[nf], sb + AKH + koff + nf * 16 * QSTR + ks * 32);
                    ldsm4(bl[nf], sb + AKL + koff + nf * 16 * QSTR + ks * 32);
                }
#pragma unroll
                for (int mf = 0; mf < 2; mf++)
#pragma unroll
                    for (int nf = 0; nf < 2; nf++) {
                        mma16816(acc[mf][2 * nf], ah[mf], bh[nf][0], bh[nf][1]);
                        mma16816(acc[mf][2 * nf], ah[mf], bl[nf][0], bl[nf][1]);
                        mma16816(acc[mf][2 * nf], al[mf], bh[nf][0], bh[nf][1]);
                        mma16816(acc[mf][2 * nf + 1], ah[mf], bh[nf][2], bh[nf][3]);
                        mma16816(acc[mf][2 * nf + 1], ah[mf], bl[nf][2], bl[nf][3]);
                        mma16816(acc[mf][2 * nf + 1], al[mf], bh[nf][2], bh[nf][3]);
                    }
            }
#pragma unroll
            for (int mf = 0; mf < 2; mf++) {
                int r0 = wm * 32 + mf * 16 + g;
                float w0 = mwp[r0], w1 = mwp[r0 + 8];
#pragma unroll
                for (int nf = 0; nf < 4; nf++) {
                    uint32_t cb = (uint32_t)((wn * 32 + nf * 8 + t4 * 2) * 4);
                    float2 v0, v1;
                    v0.x = acc[mf][nf][0] * w0;
                    v0.y = acc[mf][nf][1] * w0;
                    v1.x = acc[mf][nf][2] * w1;
                    v1.y = acc[mf][nf][3] * w1;
                    *(float2*)(smc + AS + r0 * SSTR + cb) = v0;
                    *(float2*)(smc + AS + (r0 + 8) * SSTR + cb) = v1;
                }
            }
        }
        __syncthreads();
        if (c < NKC - 1) {
            kv_issue(sb + AKH, sb + AKL,
                     g_kh + hbase + (c + 1) * 64 * DD,
                     g_kl + hbase + (c + 1) * 64 * DD, tid);
            CP_COMMIT();
        }

        // ---- Phase B: per-row top-32 + softmax; P -> bf16 hi/lo overlaid on S
#pragma unroll 1
        for (int grp = 0; grp < 4; grp++) {
            const int row0 = warp * 16 + grp * 4;
            float s0[4], s1[4], a0[4], a1[4];
#pragma unroll
            for (int r = 0; r < 4; r++) {
                const float* sr = (const float*)(smc + AS + (row0 + r) * SSTR);
                s0[r] = sr[lane];
                s1[r] = sr[lane + 32];
                a0[r] = s0[r];
                a1[r] = s1[r];
            }
#pragma unroll
            for (int size = 2; size <= 64; size <<= 1) {
#pragma unroll
                for (int stride = size >> 1; stride > 0; stride >>= 1) {
                    if (stride == 32) {
#pragma unroll
                        for (int r = 0; r < 4; r++) {
                            float lo = fminf(a0[r], a1[r]);
                            float hi = fmaxf(a0[r], a1[r]);
                            a0[r] = lo;
                            a1[r] = hi;
                        }
                    } else {
                        const bool asc0 = ((lane & size) == 0);
                        const bool asc1 = (((lane + 32) & size) == 0);
                        const bool low = ((lane & stride) == 0);
#pragma unroll
                        for (int r = 0; r < 4; r++) {
                            float o = __shfl_xor_sync(FULL, a0[r], stride);
                            a0[r] = (low == asc0) ? fminf(a0[r], o) : fmaxf(a0[r], o);
                        }
#pragma unroll
                        for (int r = 0; r < 4; r++) {
                            float o = __shfl_xor_sync(FULL, a1[r], stride);
                            a1[r] = (low == asc1) ? fminf(a1[r], o) : fmaxf(a1[r], o);
                        }
                    }
                }
            }
            float thr[4], m0[4], m1[4], mx[4];
#pragma unroll
            for (int r = 0; r < 4; r++) {
                thr[r] = __shfl_sync(FULL, a1[r], 0);
                m0[r] = (s0[r] >= thr[r]) ? s0[r] : 0.f;
                m1[r] = (s1[r] >= thr[r]) ? s1[r] : 0.f;
                mx[r] = fmaxf(m0[r], m1[r]);
            }
#pragma unroll
            for (int o = 16; o; o >>= 1)
#pragma unroll
                for (int r = 0; r < 4; r++)
                    mx[r] = fmaxf(mx[r], __shfl_xor_sync(FULL, mx[r], o));
            float e0[4], e1[4], sum[4];
#pragma unroll
            for (int r = 0; r < 4; r++) {
                e0[r] = __expf(m0[r] - mx[r]);
                e1[r] = __expf(m1[r] - mx[r]);
                sum[r] = e0[r] + e1[r];
            }
#pragma unroll
            for (int o = 16; o; o >>= 1)
#pragma unroll
                for (int r = 0; r < 4; r++)
                    sum[r] += __shfl_xor_sync(FULL, sum[r], o);
#pragma unroll
            for (int r = 0; r < 4; r++) {
                float denom = fmaxf(sum[r], 1e-6f);
                float inv = 1.f / denom;
                float p0 = e0[r] * inv, p1 = e1[r] * inv;
                bf16 h0, l0, h1, l1;
                split_bf16(p0, h0, l0);
                split_bf16(p1, h1, l1);
                char* ro = smc + AS + (row0 + r) * SSTR;
                ((bf16*)ro)[lane] = h0;
                ((bf16*)ro)[lane + 32] = h1;
                ((bf16*)(ro + 128))[lane] = l0;
                ((bf16*)(ro + 128))[lane + 32] = l1;
                if (lane == 0) psp[row0 + r] += sum[r] * inv;
            }
        }
        if (c < NKC - 1) CP_WAIT1();   // V(c) landed
        else             CP_WAIT0();
        __syncthreads();

        // ---- Phase C: O += P V (3-term bf16), V via ldmatrix.trans
#pragma unroll
        for (int ks = 0; ks < 4; ks++) {
            uint32_t ph[2][4], pl[2][4], vh[2][4], vl[2][4];
#pragma unroll
            for (int mf = 0; mf < 2; mf++) {
                ldsm4(ph[mf], sb + AS + poff + mf * 16 * SSTR + ks * 32);
                ldsm4(pl[mf], sb + AS + 128 + poff + mf * 16 * SSTR + ks * 32);
            }
#pragma unroll
            for (int nf = 0; nf < 2; nf++) {
                ldsm4t(vh[nf], sb + AVH + voff + ks * 16 * QSTR + nf * 32);
                ldsm4t(vl[nf], sb + AVL + voff + ks * 16 * QSTR + nf * 32);
            }
#pragma unroll
            for (int mf = 0; mf < 2; mf++)
#pragma unroll
                for (int nf = 0; nf < 2; nf++) {
                    mma16816(O[mf][2 * nf], ph[mf], vh[nf][0], vh[nf][1]);
                    mma16816(O[mf][2 * nf], ph[mf], vl[nf][0], vl[nf][1]);
                    mma16816(O[mf][2 * nf], pl[mf], vh[nf][0], vh[nf][1]);
                    mma16816(O[mf][2 * nf + 1], ph[mf], vh[nf][2], vh[nf][3]);
                    mma16816(O[mf][2 * nf + 1], ph[mf], vl[nf][2], vl[nf][3]);
                    mma16816(O[mf][2 * nf + 1], pl[mf], vh[nf][2], vh[nf][3]);
                }
        }
        __syncthreads();
        if (c < NKC - 1) {
            kv_issue(sb + AVH, sb + AVL,
                     g_vh + hbase + (c + 1) * 64 * DD,
                     g_vl + hbase + (c + 1) * 64 * DD, tid);
            CP_COMMIT();
        }
    }

    // Epilogue: normalize, nan2num, split bf16 -> g_ah/g_al
#pragma unroll
    for (int mf = 0; mf < 2; mf++)
#pragma unroll
        for (int rr = 0; rr < 2; rr++) {
            int row = wm * 32 + mf * 16 + g + rr * 8;
            float nrm = fmaxf(psp[row], 1e-6f);
            float inv = 1.f / nrm;
            int t = qt * 128 + row;
#pragma unroll
            for (int nf = 0; nf < 4; nf++) {
                float v0 = nan2num(O[mf][nf][rr * 2] * inv);
                float v1 = nan2num(O[mf][nf][rr * 2 + 1] * inv);
                bf16 h0, h1, l0, l1;
                split_bf16(v0, h0, l0);
                split_bf16(v1, h1, l1);
                int idx = (b * TT + t) * CCH + h * 64 + wn * 32 + nf * 8 + t4 * 2;
                *(__nv_bfloat162*)&g_ah[idx] = mkbf2(h0, h1);
                *(__nv_bfloat162*)&g_al[idx] = mkbf2(l0, l1);
            }
        }
}

// ---------------------------------------------------------------------------
extern "C" void kernel_launch(void* const* d_in, const int* in_sizes, int n_in,
                              void* d_out, int out_size)
{
    const float* x     = (const float*)d_in[0];
    const float* imp   = (const float*)d_in[1];
    const float* temps = (const float*)d_in[2];
    const float* Wq    = (const float*)d_in[3];
    const float* Wk    = (const float*)d_in[4];
    const float* Wv    = (const float*)d_in[5];
    const float* Wo    = (const float*)d_in[6];
    float* out = (float*)d_out;

    cudaFuncSetAttribute(attn_kernel,
                         cudaFuncAttributeMaxDynamicSharedMemorySize, SMEM_ATTN);
    cudaFuncSetAttribute(proj_tc_kernel,
                         cudaFuncAttributeMaxDynamicSharedMemorySize, SMEM_GEMM);
    cudaFuncSetAttribute(out_tc_kernel,
                         cudaFuncAttributeMaxDynamicSharedMemorySize, SMEM_GEMM);

    convx_kernel<<<BB * TT * CCH / 1024, 256>>>(x);
    transw_kernel<<<dim3(32, 32, 4), 256>>>(Wq, Wk, Wv, Wo);
    proj_tc_kernel<<<dim3(8, 32, 3), 256, SMEM_GEMM>>>();
    attn_kernel<<<dim3(8, HH, BB), 256, SMEM_ATTN>>>(imp, temps);
    out_tc_kernel<<<dim3(8, 32), 256, SMEM_GEMM>>>(out);
}

// round 8
// speedup vs baseline: 2.6477x; 1.2818x over previous
#include <cuda_runtime.h>
#include <cuda_bf16.h>
#include <math.h>
#include <stdint.h>

#define BB 4
#define TT 1024
#define CCH 1024
#define HH 16
#define DD 64
#define NKC 16
#define SCALE_F 0.125f

typedef unsigned long long ull;
typedef __nv_bfloat16 bf16;

// Scratch (device globals: allocation-free rule)
__device__ bf16 g_qh[BB * HH * TT * DD], g_ql[BB * HH * TT * DD];
__device__ bf16 g_kh[BB * HH * TT * DD], g_kl[BB * HH * TT * DD];
__device__ bf16 g_vh[BB * HH * TT * DD], g_vl[BB * HH * TT * DD];
__device__ bf16 g_xh[BB * TT * CCH], g_xl[BB * TT * CCH];       // x split
__device__ bf16 g_wth[4 * CCH * CCH], g_wtl[4 * CCH * CCH];     // W^T split
__device__ bf16 g_ah[BB * TT * CCH], g_al[BB * TT * CCH];       // attn split

__device__ __forceinline__ float4 ld4(const float* p) {
    return *reinterpret_cast<const float4*>(p);
}

__device__ __forceinline__ float nan2num(float v) {
    if (isnan(v)) return 0.f;
    if (isinf(v)) return v > 0.f ? 1.f : -1.f;
    return v;
}

__device__ __forceinline__ uint32_t smem_u32(const void* p) {
    uint32_t a;
    asm("{ .reg .u64 t; cvta.to.shared.u64 t, %1; cvt.u32.u64 %0, t; }"
        : "=r"(a) : "l"(p));
    return a;
}

__device__ __forceinline__ void split_bf16(float v, bf16& h, bf16& l) {
    h = __float2bfloat16(v);
    l = __float2bfloat16(v - __bfloat162float(h));
}

__device__ __forceinline__ __nv_bfloat162 mkbf2(bf16 a, bf16 b) {
    __nv_bfloat162 r;
    r.x = a;
    r.y = b;
    return r;
}

__device__ __forceinline__ uint32_t pkbf(bf16 lo16, bf16 hi16) {
    __nv_bfloat162 t = mkbf2(lo16, hi16);
    return *reinterpret_cast<uint32_t*>(&t);
}

// ---------------- mma.sync building blocks ----------------
__device__ __forceinline__ void cpa16(uint32_t s, const void* g) {
    asm volatile("cp.async.cg.shared.global [%0], [%1], 16;" :: "r"(s), "l"(g));
}
#define CP_COMMIT() asm volatile("cp.async.commit_group;")
#define CP_WAIT0() asm volatile("cp.async.wait_group 0;")
#define CP_WAIT1() asm volatile("cp.async.wait_group 1;")
#define CP_WAIT2() asm volatile("cp.async.wait_group 2;")

__device__ __forceinline__ void ldsm4(uint32_t r[4], uint32_t a) {
    asm volatile("ldmatrix.sync.aligned.m8n8.x4.shared.b16 {%0,%1,%2,%3}, [%4];"
                 : "=r"(r[0]), "=r"(r[1]), "=r"(r[2]), "=r"(r[3]) : "r"(a));
}

__device__ __forceinline__ void ldsm4t(uint32_t r[4], uint32_t a) {
    asm volatile("ldmatrix.sync.aligned.m8n8.x4.trans.shared.b16 {%0,%1,%2,%3}, [%4];"
                 : "=r"(r[0]), "=r"(r[1]), "=r"(r[2]), "=r"(r[3]) : "r"(a));
}

__device__ __forceinline__ void mma16816(float c[4], const uint32_t a[4],
                                         uint32_t b0, uint32_t b1) {
    asm volatile(
        "mma.sync.aligned.m16n8k16.row.col.f32.bf16.bf16.f32 "
        "{%0,%1,%2,%3}, {%4,%5,%6,%7}, {%8,%9}, {%0,%1,%2,%3};"
        : "+f"(c[0]), "+f"(c[1]), "+f"(c[2]), "+f"(c[3])
        : "r"(a[0]), "r"(a[1]), "r"(a[2]), "r"(a[3]), "r"(b0), "r"(b1));
}

// ---------------- dense GEMM tiling (R6/R7, proven) ----------------
#define KT 32
#define NKT 32
#define ROWB 80
#define TILE_BG (128 * ROWB)
#define STAGE_B (4 * TILE_BG)
#define NSTAGE 4
#define SMEM_GEMM (NSTAGE * STAGE_B)

__device__ __forceinline__ void stage_load(
    uint32_t sbase, int s,
    const bf16* __restrict__ Ah, const bf16* __restrict__ Al,
    const bf16* __restrict__ Bh, const bf16* __restrict__ Bl,
    int kt, int tid)
{
    uint32_t st = sbase + s * STAGE_B;
    const bf16* srcs[4] = {Ah, Al, Bh, Bl};
#pragma unroll
    for (int tI = 0; tI < 4; tI++) {
        const bf16* src = srcs[tI] + kt * KT;
        uint32_t dst = st + tI * TILE_BG;
#pragma unroll
        for (int i = 0; i < 2; i++) {
            int c = tid + i * 256;
            int row = c >> 2, seg = c & 3;
            cpa16(dst + row * ROWB + seg * 16, src + row * CCH + seg * 8);
        }
    }
}

__device__ __forceinline__ void gemm_core(
    const bf16* __restrict__ Ah, const bf16* __restrict__ Al,
    const bf16* __restrict__ Bh, const bf16* __restrict__ Bl,
    uint32_t sbase, int tid, float acc[4][4][4])
{
#pragma unroll
    for (int i = 0; i < 4; i++)
#pragma unroll
        for (int j = 0; j < 4; j++)
#pragma unroll
            for (int r = 0; r < 4; r++) acc[i][j][r] = 0.f;

    const int lane = tid & 31, warp = tid >> 5;
    const int wm = warp >> 2, wn = warp & 3;

    stage_load(sbase, 0, Ah, Al, Bh, Bl, 0, tid);
    CP_COMMIT();
    stage_load(sbase, 1, Ah, Al, Bh, Bl, 1, tid);
    CP_COMMIT();
    stage_load(sbase, 2, Ah, Al, Bh, Bl, 2, tid);
    CP_COMMIT();

    const uint32_t aoff = (uint32_t)((wm * 64 + ((lane >> 3) & 1) * 8 + (lane & 7)) * ROWB
                                     + ((lane >> 4) & 1) * 16);
    const uint32_t boff = (uint32_t)((wn * 32 + ((lane >> 4) & 1) * 8 + (lane & 7)) * ROWB
                                     + ((lane >> 3) & 1) * 16);

#pragma unroll 1
    for (int c = 0; c < NKT; c++) {
        if (c < 30)       CP_WAIT2();
        else if (c == 30) CP_WAIT1();
        else              CP_WAIT0();
        __syncthreads();
        if (c + 3 < NKT) {
            stage_load(sbase, (c + 3) & 3, Ah, Al, Bh, Bl, c + 3, tid);
            CP_COMMIT();
        }
        const uint32_t st = sbase + (c & 3) * STAGE_B;
        const uint32_t aH = st + aoff;
        const uint32_t aL = st + TILE_BG + aoff;
        const uint32_t bH = st + 2 * TILE_BG + boff;
        const uint32_t bL = st + 3 * TILE_BG + boff;
#pragma unroll
        for (int ks = 0; ks < 2; ks++) {
            const uint32_t kc = ks * 32;
            uint32_t ah[4][4], al[4][4], bh[2][4], bl[2][4];
#pragma unroll
            for (int mf = 0; mf < 4; mf++) {
                ldsm4(ah[mf], aH + mf * 16 * ROWB + kc);
                ldsm4(al[mf], aL + mf * 16 * ROWB + kc);
            }
#pragma unroll
            for (int p = 0; p < 2; p++) {
                ldsm4(bh[p], bH + p * 16 * ROWB + kc);
                ldsm4(bl[p], bL + p * 16 * ROWB + kc);
            }
#pragma unroll
            for (int mf = 0; mf < 4; mf++)
#pragma unroll
                for (int p = 0; p < 2; p++) {
                    mma16816(acc[mf][2 * p], ah[mf], bh[p][0], bh[p][1]);
                    mma16816(acc[mf][2 * p], ah[mf], bl[p][0], bl[p][1]);
                    mma16816(acc[mf][2 * p], al[mf], bh[p][0], bh[p][1]);
                    mma16816(acc[mf][2 * p + 1], ah[mf], bh[p][2], bh[p][3]);
                    mma16816(acc[mf][2 * p + 1], ah[mf], bl[p][2], bl[p][3]);
                    mma16816(acc[mf][2 * p + 1], al[mf], bh[p][2], bh[p][3]);
                }
        }
    }
}

// ---------------------------------------------------------------------------
// Prep kernels
// ---------------------------------------------------------------------------
__global__ __launch_bounds__(256) void convx_kernel(const float* __restrict__ x)
{
    int i = blockIdx.x * 256 + threadIdx.x;
    float4 v = ld4(x + i * 4);
    bf16 h0, h1, h2, h3, l0, l1, l2, l3;
    split_bf16(v.x, h0, l0);
    split_bf16(v.y, h1, l1);
    split_bf16(v.z, h2, l2);
    split_bf16(v.w, h3, l3);
    *(__nv_bfloat162*)&g_xh[i * 4] = mkbf2(h0, h1);
    *(__nv_bfloat162*)&g_xh[i * 4 + 2] = mkbf2(h2, h3);
    *(__nv_bfloat162*)&g_xl[i * 4] = mkbf2(l0, l1);
    *(__nv_bfloat162*)&g_xl[i * 4 + 2] = mkbf2(l2, l3);
}

__global__ __launch_bounds__(256) void transw_kernel(
    const float* __restrict__ Wq, const float* __restrict__ Wk,
    const float* __restrict__ Wv, const float* __restrict__ Wo)
{
    __shared__ float tile[32][33];
    const int z = blockIdx.z;
    const float* src = (z == 0) ? Wq : (z == 1) ? Wk : (z == 2) ? Wv : Wo;

    int tx = threadIdx.x & 31, ty = threadIdx.x >> 5;
    int x = blockIdx.x * 32 + tx;
    int y = blockIdx.y * 32 + ty;
#pragma unroll
    for (int j = 0; j < 32; j += 8)
        tile[ty + j][tx] = src[(y + j) * CCH + x];
    __syncthreads();
    int x2 = blockIdx.y * 32 + tx;
    int y2 = blockIdx.x * 32 + ty;
#pragma unroll
    for (int j = 0; j < 32; j += 8) {
        float v = tile[tx][ty + j];
        bf16 h, l;
        split_bf16(v, h, l);
        int idx = z * CCH * CCH + (y2 + j) * CCH + x2;
        g_wth[idx] = h;
        g_wtl[idx] = l;
    }
}

// ---------------------------------------------------------------------------
// Projection GEMM: q/k/v = x @ W{q,k,v}, dst bf16 hi/lo [B][H][T][D]
// ---------------------------------------------------------------------------
__global__ __launch_bounds__(256) void proj_tc_kernel()
{
    extern __shared__ char smem[];
    const int tid = threadIdx.x;
    const int m0 = blockIdx.y * 128;
    const int n0 = blockIdx.x * 128;
    const int z = blockIdx.z;

    const bf16* Ah = g_xh + m0 * CCH;
    const bf16* Al = g_xl + m0 * CCH;
    const bf16* Bh = g_wth + z * CCH * CCH + n0 * CCH;
    const bf16* Bl = g_wtl + z * CCH * CCH + n0 * CCH;
    bf16* dsth = (z == 0) ? g_qh : (z == 1) ? g_kh : g_vh;
    bf16* dstl = (z == 0) ? g_ql : (z == 1) ? g_kl : g_vl;

    float acc[4][4][4];
    gemm_core(Ah, Al, Bh, Bl, smem_u32(smem), tid, acc);

    const int lane = tid & 31, warp = tid >> 5;
    const int wm = warp >> 2, wn = warp & 3;
    const int g = lane >> 2, t4 = lane & 3;
    const bool isq = (z == 0);
#pragma unroll
    for (int mf = 0; mf < 4; mf++)
#pragma unroll
        for (int nf = 0; nf < 4; nf++)
#pragma unroll
            for (int rr = 0; rr < 2; rr++) {
                int m = m0 + wm * 64 + mf * 16 + g + rr * 8;
                int n = n0 + wn * 32 + nf * 8 + t4 * 2;
                int bb = m >> 10, tt = m & 1023;
                int hh = n >> 6, dd = n & 63;
                float v0 = acc[mf][nf][rr * 2];
                float v1 = acc[mf][nf][rr * 2 + 1];
                if (isq) { v0 = nan2num(v0); v1 = nan2num(v1); }
                bf16 h0, h1, l0, l1;
                split_bf16(v0, h0, l0);
                split_bf16(v1, h1, l1);
                int idx = ((bb * HH + hh) * TT + tt) * DD + dd;
                *(__nv_bfloat162*)&dsth[idx] = mkbf2(h0, h1);
                *(__nv_bfloat162*)&dstl[idx] = mkbf2(l0, l1);
            }
}

// ---------------------------------------------------------------------------
// Output GEMM: out = attn @ Wo
// ---------------------------------------------------------------------------
__global__ __launch_bounds__(256) void out_tc_kernel(float* __restrict__ out)
{
    extern __shared__ char smem[];
    const int tid = threadIdx.x;
    const int m0 = blockIdx.y * 128;
    const int n0 = blockIdx.x * 128;

    const bf16* Ah = g_ah + m0 * CCH;
    const bf16* Al = g_al + m0 * CCH;
    const bf16* Bh = g_wth + 3 * CCH * CCH + n0 * CCH;
    const bf16* Bl = g_wtl + 3 * CCH * CCH + n0 * CCH;

    float acc[4][4][4];
    gemm_core(Ah, Al, Bh, Bl, smem_u32(smem), tid, acc);

    const int lane = tid & 31, warp = tid >> 5;
    const int wm = warp >> 2, wn = warp & 3;
    const int g = lane >> 2, t4 = lane & 3;
#pragma unroll
    for (int mf = 0; mf < 4; mf++)
#pragma unroll
        for (int nf = 0; nf < 4; nf++)
#pragma unroll
            for (int rr = 0; rr < 2; rr++) {
                int m = m0 + wm * 64 + mf * 16 + g + rr * 8;
                int n = n0 + wn * 32 + nf * 8 + t4 * 2;
                float2 v;
                v.x = acc[mf][nf][rr * 2];
                v.y = acc[mf][nf][rr * 2 + 1];
                *(float2*)&out[m * CCH + n] = v;
            }
}

// ---------------------------------------------------------------------------
// Attention v2: CTA = (b, h, 128-query tile), 8 warps; each warp owns 16 FULL
// score rows (16x64 tiles). S/P stay in registers; top-32 via quad-parallel
// bitonic selection; one __syncthreads per chunk (double-buffered K/V).
// ---------------------------------------------------------------------------
#define QSTR 144
#define TILE_A (64 * QSTR)            // 9216 per K/V half tile
#define AQH 0
#define AQL (128 * QSTR)              // 18432
#define AKV (2 * 128 * QSTR)          // 36864; stage s at AKV + s*4*TILE_A
#define SMEM_ATTN (AKV + 8 * TILE_A)  // 110592

// Exact 32nd-largest (thr) and max (mx) of 64 values spread 16/lane on a quad.
__device__ __forceinline__ void sel64(const float s[16], float& thr, float& mx)
{
    const unsigned FULL = 0xffffffffu;
    const int t4 = threadIdx.x & 3;
    float v[16];
#pragma unroll
    for (int i = 0; i < 16; i++) v[i] = s[i];
    // in-thread bitonic sort ascending (10 stages, 80 comparators)
#pragma unroll
    for (int size = 2; size <= 16; size <<= 1) {
#pragma unroll
        for (int stride = size >> 1; stride >= 1; stride >>= 1) {
#pragma unroll
            for (int i = 0; i < 16; i++) {
                int j = i ^ stride;
                if (j > i) {
                    bool up = ((i & size) == 0) || (size == 16);
                    float lo = fminf(v[i], v[j]);
                    float hi = fmaxf(v[i], v[j]);
                    v[i] = up ? lo : hi;
                    v[j] = up ? hi : lo;
                }
            }
        }
    }
    // cross-lane bitonic merge (xor 1): even lane -> lower 16, odd -> upper 16
    {
        const bool lowh = ((t4 & 1) == 0);
#pragma unroll
        for (int i = 0; i < 8; i++) {
            float vi = v[i], vo = v[15 - i];
            float a = __shfl_xor_sync(FULL, vo, 1);
            float b = __shfl_xor_sync(FULL, vi, 1);
            v[i]      = lowh ? fminf(vi, a) : fmaxf(vi, a);
            v[15 - i] = lowh ? fminf(vo, b) : fmaxf(vo, b);
        }
#pragma unroll
        for (int stride = 8; stride >= 1; stride >>= 1) {
#pragma unroll
            for (int i = 0; i < 16; i++) {
                int j = i ^ stride;
                if (j > i) {
                    float lo = fminf(v[i], v[j]);
                    float hi = fmaxf(v[i], v[j]);
                    v[i] = lo;
                    v[j] = hi;
                }
            }
        }
    }
    // top-32 of the two sorted-32 lists: C_p = max(X_p, Y_{31-p}); reduce
    float mn = 1e30f, mmx = -1e30f;
#pragma unroll
    for (int i = 0; i < 8; i++) {
        float vi = v[i], vo = v[15 - i];
        float a = __shfl_xor_sync(FULL, vo, 3);
        float b = __shfl_xor_sync(FULL, vi, 3);
        float c0 = fmaxf(vi, a);
        float c1 = fmaxf(vo, b);
        mn = fminf(mn, fminf(c0, c1));
        mmx = fmaxf(mmx, fmaxf(c0, c1));
    }
    mn = fminf(mn, __shfl_xor_sync(FULL, mn, 1));
    mmx = fmaxf(mmx, __shfl_xor_sync(FULL, mmx, 1));
    thr = mn;
    mx = mmx;
}

__device__ __forceinline__ void kv_load(
    uint32_t stage, const bf16* __restrict__ kh, const bf16* __restrict__ kl,
    const bf16* __restrict__ vh, const bf16* __restrict__ vl, int tid)
{
    const bf16* srcs[4] = {kh, kl, vh, vl};
#pragma unroll
    for (int i = 0; i < 8; i++) {
        int flat = i * 256 + tid;
        int tile = flat >> 9;
        int rem = flat & 511;
        int row = rem >> 3, seg = rem & 7;
        cpa16(stage + tile * TILE_A + row * QSTR + seg * 16,
              srcs[tile] + row * 64 + seg * 8);
    }
}

__global__ __launch_bounds__(256, 2) void attn_kernel(
    const float* __restrict__ imp, const float* __restrict__ temps)
{
    extern __shared__ char smc[];
    const uint32_t sb = smem_u32(smc);

    const int qt = blockIdx.x, h = blockIdx.y, b = blockIdx.z;
    const int tid = threadIdx.x;
    const int lane = tid & 31, warp = tid >> 5;
    const int g = lane >> 2, t4 = lane & 3;
    const unsigned FULL = 0xffffffffu;

    const int hbase = ((b * HH + h) * TT) * DD;
    const int qb = hbase + qt * 128 * DD;

    // Preamble: Q + chunk-0 K/V
#pragma unroll
    for (int i = 0; i < 8; i++) {
        int flat = i * 256 + tid;
        int half = flat >> 10;
        int rem = flat & 1023;
        int row = rem >> 3, seg = rem & 7;
        const bf16* src = (half ? g_ql : g_qh) + qb + row * 64 + seg * 8;
        cpa16(sb + (half ? AQL : AQH) + row * QSTR + seg * 16, src);
    }
    kv_load(sb + AKV, g_kh + hbase, g_kl + hbase, g_vh + hbase, g_vl + hbase, tid);
    CP_COMMIT();

    // Per-thread row params (rows r0 = warp*16+g, r1 = r0+8)
    const int r0 = warp * 16 + g;
    const int r1 = r0 + 8;
    float w0, w1;
    {
        float tv = temps[b * HH + h];
        tv = fminf(fmaxf(tv, 0.1f), 100.f);
        float sc = SCALE_F / tv;
        float iv0 = imp[(b * TT + qt * 128 + r0) * HH + h];
        float iv1 = imp[(b * TT + qt * 128 + r1) * HH + h];
        float s0 = 1.f / (1.f + __expf(-iv0));
        float s1 = 1.f / (1.f + __expf(-iv1));
        w0 = sc / (1.f + __expf(-(s0 - 0.5f) * 10.f));
        w1 = sc / (1.f + __expf(-(s1 - 0.5f) * 10.f));
    }

    // ldmatrix lane offsets
    const uint32_t aoff = (uint32_t)((warp * 16 + ((lane >> 3) & 1) * 8 + (lane & 7)) * QSTR
                                     + ((lane >> 4) & 1) * 16);
    const uint32_t koff = (uint32_t)((((lane >> 4) & 1) * 8 + (lane & 7)) * QSTR
                                     + ((lane >> 3) & 1) * 16);
    const uint32_t voff = (uint32_t)((((lane >> 3) & 1) * 8 + (lane & 7)) * QSTR
                                     + ((lane >> 4) & 1) * 16);

    float O[8][4];
#pragma unroll
    for (int i = 0; i < 8; i++)
#pragma unroll
        for (int r = 0; r < 4; r++) O[i][r] = 0.f;
    float psum0 = 0.f, psum1 = 0.f;

#pragma unroll 1
    for (int c = 0; c < NKC; c++) {
        CP_WAIT0();
        __syncthreads();
        const uint32_t cur = sb + AKV + (uint32_t)(c & 1) * (4 * TILE_A);
        if (c + 1 < NKC) {
            int off = (c + 1) * 64 * DD;
            kv_load(sb + AKV + (uint32_t)((c + 1) & 1) * (4 * TILE_A),
                    g_kh + hbase + off, g_kl + hbase + off,
                    g_vh + hbase + off, g_vl + hbase + off, tid);
            CP_COMMIT();
        }

        // ---- Phase A: S(16x64) = Q K^T, 3-term bf16, acc in registers
        float acc[8][4];
#pragma unroll
        for (int i = 0; i < 8; i++)
#pragma unroll
            for (int r = 0; r < 4; r++) acc[i][r] = 0.f;
#pragma unroll
        for (int ks = 0; ks < 4; ks++) {
            uint32_t qh4[4], ql4[4];
            ldsm4(qh4, sb + AQH + aoff + ks * 32);
            ldsm4(ql4, sb + AQL + aoff + ks * 32);
#pragma unroll
            for (int nf = 0; nf < 4; nf++) {
                uint32_t kh4[4], kl4[4];
                ldsm4(kh4, cur + koff + nf * 16 * QSTR + ks * 32);
                ldsm4(kl4, cur + TILE_A + koff + nf * 16 * QSTR + ks * 32);
                mma16816(acc[2 * nf], qh4, kh4[0], kh4[1]);
                mma16816(acc[2 * nf], qh4, kl4[0], kl4[1]);
                mma16816(acc[2 * nf], ql4, kh4[0], kh4[1]);
                mma16816(acc[2 * nf + 1], qh4, kh4[2], kh4[3]);
                mma16816(acc[2 * nf + 1], qh4, kl4[2], kl4[3]);
                mma16816(acc[2 * nf + 1], ql4, kh4[2], kh4[3]);
            }
        }
#pragma unroll
        for (int nf = 0; nf < 8; nf++) {
            acc[nf][0] *= w0;
            acc[nf][1] *= w0;
            acc[nf][2] *= w1;
            acc[nf][3] *= w1;
        }

        // ---- Phase B: register-resident top-32 + softmax, per row half
#pragma unroll
        for (int rh = 0; rh < 2; rh++) {
            const int jo = rh * 2;
            float s[16];
#pragma unroll
            for (int nf = 0; nf < 8; nf++) {
                s[2 * nf] = acc[nf][jo];
                s[2 * nf + 1] = acc[nf][jo + 1];
            }
            float thr, mx;
            sel64(s, thr, mx);
            mx = fmaxf(mx, 0.f);
            float e[16];
            float sum = 0.f;
#pragma unroll
            for (int i = 0; i < 16; i++) {
                float m = (s[i] >= thr) ? s[i] : 0.f;
                e[i] = __expf(m - mx);
                sum += e[i];
            }
            sum += __shfl_xor_sync(FULL, sum, 1);
            sum += __shfl_xor_sync(FULL, sum, 2);
            float inv = 1.f / fmaxf(sum, 1e-6f);
#pragma unroll
            for (int nf = 0; nf < 8; nf++) {
                acc[nf][jo] = e[2 * nf] * inv;
                acc[nf][jo + 1] = e[2 * nf + 1] * inv;
            }
            if (rh == 0) psum0 += sum * inv;
            else         psum1 += sum * inv;
        }

        // ---- Phase C: O += P V, P from registers, V via ldmatrix.trans
#pragma unroll
        for (int ks = 0; ks < 4; ks++) {
            // Build P A-fragments for this k16 block (hi/lo split on the fly)
            uint32_t ph[4], pl[4];
            {
                bf16 h00, l00, h01, l01, h02, l02, h03, l03;
                bf16 h10, l10, h11, l11, h12, l12, h13, l13;
                split_bf16(acc[2 * ks][0], h00, l00);
                split_bf16(acc[2 * ks][1], h01, l01);
                split_bf16(acc[2 * ks + 1][0], h02, l02);
                split_bf16(acc[2 * ks + 1][1], h03, l03);
                split_bf16(acc[2 * ks][2], h10, l10);
                split_bf16(acc[2 * ks][3], h11, l11);
                split_bf16(acc[2 * ks + 1][2], h12, l12);
                split_bf16(acc[2 * ks + 1][3], h13, l13);
                ph[0] = pkbf(h00, h01); ph[1] = pkbf(h10, h11);
                ph[2] = pkbf(h02, h03); ph[3] = pkbf(h12, h13);
                pl[0] = pkbf(l00, l01); pl[1] = pkbf(l10, l11);
                pl[2] = pkbf(l02, l03); pl[3] = pkbf(l12, l13);
            }
#pragma unroll
            for (int nf = 0; nf < 4; nf++) {
                uint32_t vh4[4], vl4[4];
                ldsm4t(vh4, cur + 2 * TILE_A + voff + ks * 16 * QSTR + nf * 32);
                ldsm4t(vl4, cur + 3 * TILE_A + voff + ks * 16 * QSTR + nf * 32);
                mma16816(O[2 * nf], ph, vh4[0], vh4[1]);
                mma16816(O[2 * nf], ph, vl4[0], vl4[1]);
                mma16816(O[2 * nf], pl, vh4[0], vh4[1]);
                mma16816(O[2 * nf + 1], ph, vh4[2], vh4[3]);
                mma16816(O[2 * nf + 1], ph, vl4[2], vl4[3]);
                mma16816(O[2 * nf + 1], pl, vh4[2], vh4[3]);
            }
        }
    }

    // Epilogue: normalize, nan2num, split bf16 -> g_ah/g_al
    const float inv0 = 1.f / fmaxf(psum0, 1e-6f);
    const float inv1 = 1.f / fmaxf(psum1, 1e-6f);
    const int t0 = qt * 128 + r0;
    const int t1 = qt * 128 + r1;
#pragma unroll
    for (int nf = 0; nf < 8; nf++) {
        int colb = h * 64 + nf * 8 + t4 * 2;
        float v0 = nan2num(O[nf][0] * inv0);
        float v1 = nan2num(O[nf][1] * inv0);
        float v2 = nan2num(O[nf][2] * inv1);
        float v3 = nan2num(O[nf][3] * inv1);
        bf16 h0, l0, h1, l1, h2, l2, h3, l3;
        split_bf16(v0, h0, l0);
        split_bf16(v1, h1, l1);
        split_bf16(v2, h2, l2);
        split_bf16(v3, h3, l3);
        int i0 = (b * TT + t0) * CCH + colb;
        int i1 = (b * TT + t1) * CCH + colb;
        *(__nv_bfloat162*)&g_ah[i0] = mkbf2(h0, h1);
        *(__nv_bfloat162*)&g_al[i0] = mkbf2(l0, l1);
        *(__nv_bfloat162*)&g_ah[i1] = mkbf2(h2, h3);
        *(__nv_bfloat162*)&g_al[i1] = mkbf2(l2, l3);
    }
}

// ---------------------------------------------------------------------------
extern "C" void kernel_launch(void* const* d_in, const int* in_sizes, int n_in,
                              void* d_out, int out_size)
{
    const float* x     = (const float*)d_in[0];
    const float* imp   = (const float*)d_in[1];
    const float* temps = (const float*)d_in[2];
    const float* Wq    = (const float*)d_in[3];
    const float* Wk    = (const float*)d_in[4];
    const float* Wv    = (const float*)d_in[5];
    const float* Wo    = (const float*)d_in[6];
    float* out = (float*)d_out;

    cudaFuncSetAttribute(attn_kernel,
                         cudaFuncAttributeMaxDynamicSharedMemorySize, SMEM_ATTN);
    cudaFuncSetAttribute(proj_tc_kernel,
                         cudaFuncAttributeMaxDynamicSharedMemorySize, SMEM_GEMM);
    cudaFuncSetAttribute(out_tc_kernel,
                         cudaFuncAttributeMaxDynamicSharedMemorySize, SMEM_GEMM);

    convx_kernel<<<BB * TT * CCH / 1024, 256>>>(x);
    transw_kernel<<<dim3(32, 32, 4), 256>>>(Wq, Wk, Wv, Wo);
    proj_tc_kernel<<<dim3(8, 32, 3), 256, SMEM_GEMM>>>();
    attn_kernel<<<dim3(8, HH, BB), 256, SMEM_ATTN>>>(imp, temps);
    out_tc_kernel<<<dim3(8, 32), 256, SMEM_GEMM>>>(out);
}

// round 11
// speedup vs baseline: 2.9656x; 1.1201x over previous
#include <cuda_runtime.h>
#include <cuda_bf16.h>
#include <math.h>
#include <stdint.h>

#define BB 4
#define TT 1024
#define CCH 1024
#define HH 16
#define DD 64
#define NKC 16
#define SCALE_F 0.125f

typedef unsigned long long ull;
typedef __nv_bfloat16 bf16;

// Scratch (device globals: allocation-free rule)
__device__ bf16 g_qh[BB * HH * TT * DD], g_ql[BB * HH * TT * DD];
__device__ bf16 g_kh[BB * HH * TT * DD], g_kl[BB * HH * TT * DD];
__device__ bf16 g_vh[BB * HH * TT * DD], g_vl[BB * HH * TT * DD];
__device__ bf16 g_xh[BB * TT * CCH], g_xl[BB * TT * CCH];       // x split
__device__ bf16 g_wth[4 * CCH * CCH], g_wtl[4 * CCH * CCH];     // W^T split
__device__ bf16 g_ah[BB * TT * CCH], g_al[BB * TT * CCH];       // attn split

__device__ __forceinline__ float4 ld4(const float* p) {
    return *reinterpret_cast<const float4*>(p);
}

__device__ __forceinline__ float nan2num(float v) {
    if (isnan(v)) return 0.f;
    if (isinf(v)) return v > 0.f ? 1.f : -1.f;
    return v;
}

__device__ __forceinline__ uint32_t smem_u32(const void* p) {
    uint32_t a;
    asm("{ .reg .u64 t; cvta.to.shared.u64 t, %1; cvt.u32.u64 %0, t; }"
        : "=r"(a) : "l"(p));
    return a;
}

__device__ __forceinline__ void split_bf16(float v, bf16& h, bf16& l) {
    h = __float2bfloat16(v);
    l = __float2bfloat16(v - __bfloat162float(h));
}

__device__ __forceinline__ __nv_bfloat162 mkbf2(bf16 a, bf16 b) {
    __nv_bfloat162 r;
    r.x = a;
    r.y = b;
    return r;
}

__device__ __forceinline__ uint32_t pkbf(bf16 lo16, bf16 hi16) {
    __nv_bfloat162 t = mkbf2(lo16, hi16);
    return *reinterpret_cast<uint32_t*>(&t);
}

// ---------------- mma.sync building blocks ----------------
__device__ __forceinline__ void cpa16(uint32_t s, const void* g) {
    asm volatile("cp.async.cg.shared.global [%0], [%1], 16;" :: "r"(s), "l"(g));
}
#define CP_COMMIT() asm volatile("cp.async.commit_group;")
#define CP_WAIT0() asm volatile("cp.async.wait_group 0;")

__device__ __forceinline__ void ldsm4(uint32_t r[4], uint32_t a) {
    asm volatile("ldmatrix.sync.aligned.m8n8.x4.shared.b16 {%0,%1,%2,%3}, [%4];"
                 : "=r"(r[0]), "=r"(r[1]), "=r"(r[2]), "=r"(r[3]) : "r"(a));
}

__device__ __forceinline__ void ldsm4t(uint32_t r[4], uint32_t a) {
    asm volatile("ldmatrix.sync.aligned.m8n8.x4.trans.shared.b16 {%0,%1,%2,%3}, [%4];"
                 : "=r"(r[0]), "=r"(r[1]), "=r"(r[2]), "=r"(r[3]) : "r"(a));
}

__device__ __forceinline__ void mma16816(float c[4], const uint32_t a[4],
                                         uint32_t b0, uint32_t b1) {
    asm volatile(
        "mma.sync.aligned.m16n8k16.row.col.f32.bf16.bf16.f32 "
        "{%0,%1,%2,%3}, {%4,%5,%6,%7}, {%8,%9}, {%0,%1,%2,%3};"
        : "+f"(c[0]), "+f"(c[1]), "+f"(c[2]), "+f"(c[3])
        : "r"(a[0]), "r"(a[1]), "r"(a[2]), "r"(a[3]), "r"(b0), "r"(b1));
}

// ---------------- dense GEMM tiling: 2-stage, 2 CTAs/SM ----------------
#define KT 32
#define NKT 32
#define ROWB 80
#define TILE_BG (128 * ROWB)
#define STAGE_B (4 * TILE_BG)
#define NSTAGE 2
#define SMEM_GEMM (NSTAGE * STAGE_B)   // 81920

__device__ __forceinline__ void stage_load(
    uint32_t sbase, int s,
    const bf16* __restrict__ Ah, const bf16* __restrict__ Al,
    const bf16* __restrict__ Bh, const bf16* __restrict__ Bl,
    int kt, int tid)
{
    uint32_t st = sbase + s * STAGE_B;
    const bf16* srcs[4] = {Ah, Al, Bh, Bl};
#pragma unroll
    for (int tI = 0; tI < 4; tI++) {
        const bf16* src = srcs[tI] + kt * KT;
        uint32_t dst = st + tI * TILE_BG;
#pragma unroll
        for (int i = 0; i < 2; i++) {
            int c = tid + i * 256;
            int row = c >> 2, seg = c & 3;
            cpa16(dst + row * ROWB + seg * 16, src + row * CCH + seg * 8);
        }
    }
}

__device__ __forceinline__ void gemm_core(
    const bf16* __restrict__ Ah, const bf16* __restrict__ Al,
    const bf16* __restrict__ Bh, const bf16* __restrict__ Bl,
    uint32_t sbase, int tid, float acc[4][4][4])
{
#pragma unroll
    for (int i = 0; i < 4; i++)
#pragma unroll
        for (int j = 0; j < 4; j++)
#pragma unroll
            for (int r = 0; r < 4; r++) acc[i][j][r] = 0.f;

    const int lane = tid & 31, warp = tid >> 5;
    const int wm = warp >> 2, wn = warp & 3;

    stage_load(sbase, 0, Ah, Al, Bh, Bl, 0, tid);
    CP_COMMIT();

    const uint32_t aoff = (uint32_t)((wm * 64 + ((lane >> 3) & 1) * 8 + (lane & 7)) * ROWB
                                     + ((lane >> 4) & 1) * 16);
    const uint32_t boff = (uint32_t)((wn * 32 + ((lane >> 4) & 1) * 8 + (lane & 7)) * ROWB
                                     + ((lane >> 3) & 1) * 16);

#pragma unroll 1
    for (int c = 0; c < NKT; c++) {
        CP_WAIT0();
        __syncthreads();
        if (c + 1 < NKT) {
            stage_load(sbase, (c + 1) & 1, Ah, Al, Bh, Bl, c + 1, tid);
            CP_COMMIT();
        }
        const uint32_t st = sbase + (uint32_t)(c & 1) * STAGE_B;
        const uint32_t aH = st + aoff;
        const uint32_t aL = st + TILE_BG + aoff;
        const uint32_t bH = st + 2 * TILE_BG + boff;
        const uint32_t bL = st + 3 * TILE_BG + boff;
#pragma unroll
        for (int ks = 0; ks < 2; ks++) {
            const uint32_t kc = ks * 32;
            uint32_t bh[2][4], bl[2][4];
#pragma unroll
            for (int p = 0; p < 2; p++) {
                ldsm4(bh[p], bH + p * 16 * ROWB + kc);
                ldsm4(bl[p], bL + p * 16 * ROWB + kc);
            }
#pragma unroll
            for (int mf = 0; mf < 4; mf++) {
                uint32_t ah4[4], al4[4];
                ldsm4(ah4, aH + mf * 16 * ROWB + kc);
                ldsm4(al4, aL + mf * 16 * ROWB + kc);
#pragma unroll
                for (int p = 0; p < 2; p++) {
                    mma16816(acc[mf][2 * p], ah4, bh[p][0], bh[p][1]);
                    mma16816(acc[mf][2 * p], ah4, bl[p][0], bl[p][1]);
                    mma16816(acc[mf][2 * p], al4, bh[p][0], bh[p][1]);
                    mma16816(acc[mf][2 * p + 1], ah4, bh[p][2], bh[p][3]);
                    mma16816(acc[mf][2 * p + 1], ah4, bl[p][2], bl[p][3]);
                    mma16816(acc[mf][2 * p + 1], al4, bh[p][2], bh[p][3]);
                }
            }
        }
    }
}

// ---------------------------------------------------------------------------
// Prep kernels
// ---------------------------------------------------------------------------
__global__ __launch_bounds__(256) void convx_kernel(const float* __restrict__ x)
{
    int i = blockIdx.x * 256 + threadIdx.x;
    float4 v = ld4(x + i * 4);
    bf16 h0, h1, h2, h3, l0, l1, l2, l3;
    split_bf16(v.x, h0, l0);
    split_bf16(v.y, h1, l1);
    split_bf16(v.z, h2, l2);
    split_bf16(v.w, h3, l3);
    *(__nv_bfloat162*)&g_xh[i * 4] = mkbf2(h0, h1);
    *(__nv_bfloat162*)&g_xh[i * 4 + 2] = mkbf2(h2, h3);
    *(__nv_bfloat162*)&g_xl[i * 4] = mkbf2(l0, l1);
    *(__nv_bfloat162*)&g_xl[i * 4 + 2] = mkbf2(l2, l3);
}

__global__ __launch_bounds__(256) void transw_kernel(
    const float* __restrict__ Wq, const float* __restrict__ Wk,
    const float* __restrict__ Wv, const float* __restrict__ Wo)
{
    __shared__ float tile[32][33];
    const int z = blockIdx.z;
    const float* src = (z == 0) ? Wq : (z == 1) ? Wk : (z == 2) ? Wv : Wo;

    int tx = threadIdx.x & 31, ty = threadIdx.x >> 5;
    int x = blockIdx.x * 32 + tx;
    int y = blockIdx.y * 32 + ty;
#pragma unroll
    for (int j = 0; j < 32; j += 8)
        tile[ty + j][tx] = src[(y + j) * CCH + x];
    __syncthreads();
    int x2 = blockIdx.y * 32 + tx;
    int y2 = blockIdx.x * 32 + ty;
#pragma unroll
    for (int j = 0; j < 32; j += 8) {
        float v = tile[tx][ty + j];
        bf16 h, l;
        split_bf16(v, h, l);
        int idx = z * CCH * CCH + (y2 + j) * CCH + x2;
        g_wth[idx] = h;
        g_wtl[idx] = l;
    }
}

// ---------------------------------------------------------------------------
// Projection GEMM: q/k/v = x @ W{q,k,v}, dst bf16 hi/lo [B][H][T][D]
// ---------------------------------------------------------------------------
__global__ __launch_bounds__(256, 2) void proj_tc_kernel()
{
    extern __shared__ char smem[];
    const int tid = threadIdx.x;
    const int m0 = blockIdx.y * 128;
    const int n0 = blockIdx.x * 128;
    const int z = blockIdx.z;

    const bf16* Ah = g_xh + m0 * CCH;
    const bf16* Al = g_xl + m0 * CCH;
    const bf16* Bh = g_wth + z * CCH * CCH + n0 * CCH;
    const bf16* Bl = g_wtl + z * CCH * CCH + n0 * CCH;
    bf16* dsth = (z == 0) ? g_qh : (z == 1) ? g_kh : g_vh;
    bf16* dstl = (z == 0) ? g_ql : (z == 1) ? g_kl : g_vl;

    float acc[4][4][4];
    gemm_core(Ah, Al, Bh, Bl, smem_u32(smem), tid, acc);

    const int lane = tid & 31, warp = tid >> 5;
    const int wm = warp >> 2, wn = warp & 3;
    const int g = lane >> 2, t4 = lane & 3;
    const bool isq = (z == 0);
#pragma unroll
    for (int mf = 0; mf < 4; mf++)
#pragma unroll
        for (int nf = 0; nf < 4; nf++)
#pragma unroll
            for (int rr = 0; rr < 2; rr++) {
                int m = m0 + wm * 64 + mf * 16 + g + rr * 8;
                int n = n0 + wn * 32 + nf * 8 + t4 * 2;
                int bb = m >> 10, tt = m & 1023;
                int hh = n >> 6, dd = n & 63;
                float v0 = acc[mf][nf][rr * 2];
                float v1 = acc[mf][nf][rr * 2 + 1];
                if (isq) { v0 = nan2num(v0); v1 = nan2num(v1); }
                bf16 h0, h1, l0, l1;
                split_bf16(v0, h0, l0);
                split_bf16(v1, h1, l1);
                int idx = ((bb * HH + hh) * TT + tt) * DD + dd;
                *(__nv_bfloat162*)&dsth[idx] = mkbf2(h0, h1);
                *(__nv_bfloat162*)&dstl[idx] = mkbf2(l0, l1);
            }
}

// ---------------------------------------------------------------------------
// Output GEMM: out = attn @ Wo
// ---------------------------------------------------------------------------
__global__ __launch_bounds__(256, 2) void out_tc_kernel(float* __restrict__ out)
{
    extern __shared__ char smem[];
    const int tid = threadIdx.x;
    const int m0 = blockIdx.y * 128;
    const int n0 = blockIdx.x * 128;

    const bf16* Ah = g_ah + m0 * CCH;
    const bf16* Al = g_al + m0 * CCH;
    const bf16* Bh = g_wth + 3 * CCH * CCH + n0 * CCH;
    const bf16* Bl = g_wtl + 3 * CCH * CCH + n0 * CCH;

    float acc[4][4][4];
    gemm_core(Ah, Al, Bh, Bl, smem_u32(smem), tid, acc);

    const int lane = tid & 31, warp = tid >> 5;
    const int wm = warp >> 2, wn = warp & 3;
    const int g = lane >> 2, t4 = lane & 3;
#pragma unroll
    for (int mf = 0; mf < 4; mf++)
#pragma unroll
        for (int nf = 0; nf < 4; nf++)
#pragma unroll
            for (int rr = 0; rr < 2; rr++) {
                int m = m0 + wm * 64 + mf * 16 + g + rr * 8;
                int n = n0 + wn * 32 + nf * 8 + t4 * 2;
                float2 v;
                v.x = acc[mf][nf][rr * 2];
                v.y = acc[mf][nf][rr * 2 + 1];
                *(float2*)&out[m * CCH + n] = v;
            }
}

// ---------------------------------------------------------------------------
// Attention v2 (R8, proven): CTA = (b, h, 128-query tile), 8 warps; each warp
// owns 16 full score rows. S/P in registers; top-32 via quad-parallel bitonic
// selection; one __syncthreads per chunk (double-buffered K/V).
// ---------------------------------------------------------------------------
#define QSTR 144
#define TILE_A (64 * QSTR)
#define AQH 0
#define AQL (128 * QSTR)
#define AKV (2 * 128 * QSTR)
#define SMEM_ATTN (AKV + 8 * TILE_A)

// Exact 32nd-largest (thr) and max (mx) of 64 values spread 16/lane on a quad.
__device__ __forceinline__ void sel64(const float s[16], float& thr, float& mx)
{
    const unsigned FULL = 0xffffffffu;
    const int t4 = threadIdx.x & 3;
    float v[16];
#pragma unroll
    for (int i = 0; i < 16; i++) v[i] = s[i];
#pragma unroll
    for (int size = 2; size <= 16; size <<= 1) {
#pragma unroll
        for (int stride = size >> 1; stride >= 1; stride >>= 1) {
#pragma unroll
            for (int i = 0; i < 16; i++) {
                int j = i ^ stride;
                if (j > i) {
                    bool up = ((i & size) == 0) || (size == 16);
                    float lo = fminf(v[i], v[j]);
                    float hi = fmaxf(v[i], v[j]);
                    v[i] = up ? lo : hi;
                    v[j] = up ? hi : lo;
                }
            }
        }
    }
    {
        const bool lowh = ((t4 & 1) == 0);
#pragma unroll
        for (int i = 0; i < 8; i++) {
            float vi = v[i], vo = v[15 - i];
            float a = __shfl_xor_sync(FULL, vo, 1);
            float b = __shfl_xor_sync(FULL, vi, 1);
            v[i]      = lowh ? fminf(vi, a) : fmaxf(vi, a);
            v[15 - i] = lowh ? fminf(vo, b) : fmaxf(vo, b);
        }
#pragma unroll
        for (int stride = 8; stride >= 1; stride >>= 1) {
#pragma unroll
            for (int i = 0; i < 16; i++) {
                int j = i ^ stride;
                if (j > i) {
                    float lo = fminf(v[i], v[j]);
                    float hi = fmaxf(v[i], v[j]);
                    v[i] = lo;
                    v[j] = hi;
                }
            }
        }
    }
    float mn = 1e30f, mmx = -1e30f;
#pragma unroll
    for (int i = 0; i < 8; i++) {
        float vi = v[i], vo = v[15 - i];
        float a = __shfl_xor_sync(FULL, vo, 3);
        float b = __shfl_xor_sync(FULL, vi, 3);
        float c0 = fmaxf(vi, a);
        float c1 = fmaxf(vo, b);
        mn = fminf(mn, fminf(c0, c1));
        mmx = fmaxf(mmx, fmaxf(c0, c1));
    }
    mn = fminf(mn, __shfl_xor_sync(FULL, mn, 1));
    mmx = fmaxf(mmx, __shfl_xor_sync(FULL, mmx, 1));
    thr = mn;
    mx = mmx;
}

__device__ __forceinline__ void kv_load(
    uint32_t stage, const bf16* __restrict__ kh, const bf16* __restrict__ kl,
    const bf16* __restrict__ vh, const bf16* __restrict__ vl, int tid)
{
    const bf16* srcs[4] = {kh, kl, vh, vl};
#pragma unroll
    for (int i = 0; i < 8; i++) {
        int flat = i * 256 + tid;
        int tile = flat >> 9;
        int rem = flat & 511;
        int row = rem >> 3, seg = rem & 7;
        cpa16(stage + tile * TILE_A + row * QSTR + seg * 16,
              srcs[tile] + row * 64 + seg * 8);
    }
}

__global__ __launch_bounds__(256, 2) void attn_kernel(
    const float* __restrict__ imp, const float* __restrict__ temps)
{
    extern __shared__ char smc[];
    const uint32_t sb = smem_u32(smc);

    const int qt = blockIdx.x, h = blockIdx.y, b = blockIdx.z;
    const int tid = threadIdx.x;
    const int lane = tid & 31, warp = tid >> 5;
    const int g = lane >> 2, t4 = lane & 3;
    const unsigned FULL = 0xffffffffu;

    const int hbase = ((b * HH + h) * TT) * DD;
    const int qb = hbase + qt * 128 * DD;

#pragma unroll
    for (int i = 0; i < 8; i++) {
        int flat = i * 256 + tid;
        int half = flat >> 10;
        int rem = flat & 1023;
        int row = rem >> 3, seg = rem & 7;
        const bf16* src = (half ? g_ql : g_qh) + qb + row * 64 + seg * 8;
        cpa16(sb + (half ? AQL : AQH) + row * QSTR + seg * 16, src);
    }
    kv_load(sb + AKV, g_kh + hbase, g_kl + hbase, g_vh + hbase, g_vl + hbase, tid);
    CP_COMMIT();

    const int r0 = warp * 16 + g;
    const int r1 = r0 + 8;
    float w0, w1;
    {
        float tv = temps[b * HH + h];
        tv = fminf(fmaxf(tv, 0.1f), 100.f);
        float sc = SCALE_F / tv;
        float iv0 = imp[(b * TT + qt * 128 + r0) * HH + h];
        float iv1 = imp[(b * TT + qt * 128 + r1) * HH + h];
        float s0 = 1.f / (1.f + __expf(-iv0));
        float s1 = 1.f / (1.f + __expf(-iv1));
        w0 = sc / (1.f + __expf(-(s0 - 0.5f) * 10.f));
        w1 = sc / (1.f + __expf(-(s1 - 0.5f) * 10.f));
    }

    const uint32_t aoff = (uint32_t)((warp * 16 + ((lane >> 3) & 1) * 8 + (lane & 7)) * QSTR
                                     + ((lane >> 4) & 1) * 16);
    const uint32_t koff = (uint32_t)((((lane >> 4) & 1) * 8 + (lane & 7)) * QSTR
                                     + ((lane >> 3) & 1) * 16);
    const uint32_t voff = (uint32_t)((((lane >> 3) & 1) * 8 + (lane & 7)) * QSTR
                                     + ((lane >> 4) & 1) * 16);

    float O[8][4];
#pragma unroll
    for (int i = 0; i < 8; i++)
#pragma unroll
        for (int r = 0; r < 4; r++) O[i][r] = 0.f;
    float psum0 = 0.f, psum1 = 0.f;

#pragma unroll 1
    for (int c = 0; c < NKC; c++) {
        CP_WAIT0();
        __syncthreads();
        const uint32_t cur = sb + AKV + (uint32_t)(c & 1) * (4 * TILE_A);
        if (c + 1 < NKC) {
            int off = (c + 1) * 64 * DD;
            kv_load(sb + AKV + (uint32_t)((c + 1) & 1) * (4 * TILE_A),
                    g_kh + hbase + off, g_kl + hbase + off,
                    g_vh + hbase + off, g_vl + hbase + off, tid);
            CP_COMMIT();
        }

        float acc[8][4];
#pragma unroll
        for (int i = 0; i < 8; i++)
#pragma unroll
            for (int r = 0; r < 4; r++) acc[i][r] = 0.f;
#pragma unroll
        for (int ks = 0; ks < 4; ks++) {
            uint32_t qh4[4], ql4[4];
            ldsm4(qh4, sb + AQH + aoff + ks * 32);
            ldsm4(ql4, sb + AQL + aoff + ks * 32);
#pragma unroll
            for (int nf = 0; nf < 4; nf++) {
                uint32_t kh4[4], kl4[4];
                ldsm4(kh4, cur + koff + nf * 16 * QSTR + ks * 32);
                ldsm4(kl4, cur + TILE_A + koff + nf * 16 * QSTR + ks * 32);
                mma16816(acc[2 * nf], qh4, kh4[0], kh4[1]);
                mma16816(acc[2 * nf], qh4, kl4[0], kl4[1]);
                mma16816(acc[2 * nf], ql4, kh4[0], kh4[1]);
                mma16816(acc[2 * nf + 1], qh4, kh4[2], kh4[3]);
                mma16816(acc[2 * nf + 1], qh4, kl4[2], kl4[3]);
                mma16816(acc[2 * nf + 1], ql4, kh4[2], kh4[3]);
            }
        }
#pragma unroll
        for (int nf = 0; nf < 8; nf++) {
            acc[nf][0] *= w0;
            acc[nf][1] *= w0;
            acc[nf][2] *= w1;
            acc[nf][3] *= w1;
        }

#pragma unroll
        for (int rh = 0; rh < 2; rh++) {
            const int jo = rh * 2;
            float s[16];
#pragma unroll
            for (int nf = 0; nf < 8; nf++) {
                s[2 * nf] = acc[nf][jo];
                s[2 * nf + 1] = acc[nf][jo + 1];
            }
            float thr, mx;
            sel64(s, thr, mx);
            mx = fmaxf(mx, 0.f);
            float e[16];
            float sum = 0.f;
#pragma unroll
            for (int i = 0; i < 16; i++) {
                float m = (s[i] >= thr) ? s[i] : 0.f;
                e[i] = __expf(m - mx);
                sum += e[i];
            }
            sum += __shfl_xor_sync(FULL, sum, 1);
            sum += __shfl_xor_sync(FULL, sum, 2);
            float inv = 1.f / fmaxf(sum, 1e-6f);
#pragma unroll
            for (int nf = 0; nf < 8; nf++) {
                acc[nf][jo] = e[2 * nf] * inv;
                acc[nf][jo + 1] = e[2 * nf + 1] * inv;
            }
            if (rh == 0) psum0 += sum * inv;
            else         psum1 += sum * inv;
        }

#pragma unroll
        for (int ks = 0; ks < 4; ks++) {
            uint32_t ph[4], pl[4];
            {
                bf16 h00, l00, h01, l01, h02, l02, h03, l03;
                bf16 h10, l10, h11, l11, h12, l12, h13, l13;
                split_bf16(acc[2 * ks][0], h00, l00);
                split_bf16(acc[2 * ks][1], h01, l01);
                split_bf16(acc[2 * ks + 1][0], h02, l02);
                split_bf16(acc[2 * ks + 1][1], h03, l03);
                split_bf16(acc[2 * ks][2], h10, l10);
                split_bf16(acc[2 * ks][3], h11, l11);
                split_bf16(acc[2 * ks + 1][2], h12, l12);
                split_bf16(acc[2 * ks + 1][3], h13, l13);
                ph[0] = pkbf(h00, h01); ph[1] = pkbf(h10, h11);
                ph[2] = pkbf(h02, h03); ph[3] = pkbf(h12, h13);
                pl[0] = pkbf(l00, l01); pl[1] = pkbf(l10, l11);
                pl[2] = pkbf(l02, l03); pl[3] = pkbf(l12, l13);
            }
#pragma unroll
            for (int nf = 0; nf < 4; nf++) {
                uint32_t vh4[4], vl4[4];
                ldsm4t(vh4, cur + 2 * TILE_A + voff + ks * 16 * QSTR + nf * 32);
                ldsm4t(vl4, cur + 3 * TILE_A + voff + ks * 16 * QSTR + nf * 32);
                mma16816(O[2 * nf], ph, vh4[0], vh4[1]);
                mma16816(O[2 * nf], ph, vl4[0], vl4[1]);
                mma16816(O[2 * nf], pl, vh4[0], vh4[1]);
                mma16816(O[2 * nf + 1], ph, vh4[2], vh4[3]);
                mma16816(O[2 * nf + 1], ph, vl4[2], vl4[3]);
                mma16816(O[2 * nf + 1], pl, vh4[2], vh4[3]);
            }
        }
    }

    const float inv0 = 1.f / fmaxf(psum0, 1e-6f);
    const float inv1 = 1.f / fmaxf(psum1, 1e-6f);
    const int t0 = qt * 128 + r0;
    const int t1 = qt * 128 + r1;
#pragma unroll
    for (int nf = 0; nf < 8; nf++) {
        int colb = h * 64 + nf * 8 + t4 * 2;
        float v0 = nan2num(O[nf][0] * inv0);
        float v1 = nan2num(O[nf][1] * inv0);
        float v2 = nan2num(O[nf][2] * inv1);
        float v3 = nan2num(O[nf][3] * inv1);
        bf16 h0, l0, h1, l1, h2, l2, h3, l3;
        split_bf16(v0, h0, l0);
        split_bf16(v1, h1, l1);
        split_bf16(v2, h2, l2);
        split_bf16(v3, h3, l3);
        int i0 = (b * TT + t0) * CCH + colb;
        int i1 = (b * TT + t1) * CCH + colb;
        *(__nv_bfloat162*)&g_ah[i0] = mkbf2(h0, h1);
        *(__nv_bfloat162*)&g_al[i0] = mkbf2(l0, l1);
        *(__nv_bfloat162*)&g_ah[i1] = mkbf2(h2, h3);
        *(__nv_bfloat162*)&g_al[i1] = mkbf2(l2, l3);
    }
}

// ---------------------------------------------------------------------------
extern "C" void kernel_launch(void* const* d_in, const int* in_sizes, int n_in,
                              void* d_out, int out_size)
{
    const float* x     = (const float*)d_in[0];
    const float* imp   = (const float*)d_in[1];
    const float* temps = (const float*)d_in[2];
    const float* Wq    = (const float*)d_in[3];
    const float* Wk    = (const float*)d_in[4];
    const float* Wv    = (const float*)d_in[5];
    const float* Wo    = (const float*)d_in[6];
    float* out = (float*)d_out;

    cudaFuncSetAttribute(attn_kernel,
                         cudaFuncAttributeMaxDynamicSharedMemorySize, SMEM_ATTN);
    cudaFuncSetAttribute(proj_tc_kernel,
                         cudaFuncAttributeMaxDynamicSharedMemorySize, SMEM_GEMM);
    cudaFuncSetAttribute(out_tc_kernel,
                         cudaFuncAttributeMaxDynamicSharedMemorySize, SMEM_GEMM);

    convx_kernel<<<BB * TT * CCH / 1024, 256>>>(x);
    transw_kernel<<<dim3(32, 32, 4), 256>>>(Wq, Wk, Wv, Wo);
    proj_tc_kernel<<<dim3(8, 32, 3), 256, SMEM_GEMM>>>();
    attn_kernel<<<dim3(8, HH, BB), 256, SMEM_ATTN>>>(imp, temps);
    out_tc_kernel<<<dim3(8, 32), 256, SMEM_GEMM>>>(out);
}

// round 12
// speedup vs baseline: 3.4014x; 1.1469x over previous
#include <cuda_runtime.h>
#include <cuda_bf16.h>
#include <cuda_fp16.h>
#include <math.h>
#include <stdint.h>

#define BB 4
#define TT 1024
#define CCH 1024
#define HH 16
#define DD 64
#define NKC 16
#define SCALE_F 0.125f

typedef unsigned long long ull;
typedef __nv_bfloat16 bf16;
typedef __half h16;

// Scratch (device globals: allocation-free rule)
__device__ bf16 g_qh[BB * HH * TT * DD], g_ql[BB * HH * TT * DD];
__device__ bf16 g_kh[BB * HH * TT * DD], g_kl[BB * HH * TT * DD];
__device__ h16  g_vf[BB * HH * TT * DD];                        // V single fp16
__device__ bf16 g_xh[BB * TT * CCH], g_xl[BB * TT * CCH];       // x bf16 split
__device__ h16  g_fxh[BB * TT * CCH], g_fxl[BB * TT * CCH];     // x fp16 split
__device__ bf16 g_wth[2 * CCH * CCH], g_wtl[2 * CCH * CCH];     // Wq,Wk^T bf16 split
__device__ h16  g_wvf[CCH * CCH], g_wof[CCH * CCH];             // Wv,Wo^T fp16 single
__device__ h16  g_ah[BB * TT * CCH], g_al[BB * TT * CCH];       // attn fp16 split

__device__ __forceinline__ float4 ld4(const float* p) {
    return *reinterpret_cast<const float4*>(p);
}

__device__ __forceinline__ float nan2num(float v) {
    if (isnan(v)) return 0.f;
    if (isinf(v)) return v > 0.f ? 1.f : -1.f;
    return v;
}

__device__ __forceinline__ uint32_t smem_u32(const void* p) {
    uint32_t a;
    asm("{ .reg .u64 t; cvta.to.shared.u64 t, %1; cvt.u32.u64 %0, t; }"
        : "=r"(a) : "l"(p));
    return a;
}

__device__ __forceinline__ void split_bf16(float v, bf16& h, bf16& l) {
    h = __float2bfloat16(v);
    l = __float2bfloat16(v - __bfloat162float(h));
}

__device__ __forceinline__ void split_f16(float v, h16& h, h16& l) {
    h = __float2half_rn(v);
    l = __float2half_rn(v - __half2float(h));
}

__device__ __forceinline__ __nv_bfloat162 mkbf2(bf16 a, bf16 b) {
    __nv_bfloat162 r;
    r.x = a;
    r.y = b;
    return r;
}

__device__ __forceinline__ __half2 mkh2(h16 a, h16 b) {
    __half2 r;
    r.x = a;
    r.y = b;
    return r;
}

__device__ __forceinline__ uint32_t pkh(h16 a, h16 b) {
    __half2 t = mkh2(a, b);
    return *reinterpret_cast<uint32_t*>(&t);
}

// ---------------- mma.sync building blocks ----------------
__device__ __forceinline__ void cpa16(uint32_t s, const void* g) {
    asm volatile("cp.async.cg.shared.global [%0], [%1], 16;" :: "r"(s), "l"(g));
}
#define CP_COMMIT() asm volatile("cp.async.commit_group;")
#define CP_WAIT0() asm volatile("cp.async.wait_group 0;")

__device__ __forceinline__ void ldsm4(uint32_t r[4], uint32_t a) {
    asm volatile("ldmatrix.sync.aligned.m8n8.x4.shared.b16 {%0,%1,%2,%3}, [%4];"
                 : "=r"(r[0]), "=r"(r[1]), "=r"(r[2]), "=r"(r[3]) : "r"(a));
}

__device__ __forceinline__ void ldsm4t(uint32_t r[4], uint32_t a) {
    asm volatile("ldmatrix.sync.aligned.m8n8.x4.trans.shared.b16 {%0,%1,%2,%3}, [%4];"
                 : "=r"(r[0]), "=r"(r[1]), "=r"(r[2]), "=r"(r[3]) : "r"(a));
}

__device__ __forceinline__ void mma16816(float c[4], const uint32_t a[4],
                                         uint32_t b0, uint32_t b1) {
    asm volatile(
        "mma.sync.aligned.m16n8k16.row.col.f32.bf16.bf16.f32 "
        "{%0,%1,%2,%3}, {%4,%5,%6,%7}, {%8,%9}, {%0,%1,%2,%3};"
        : "+f"(c[0]), "+f"(c[1]), "+f"(c[2]), "+f"(c[3])
        : "r"(a[0]), "r"(a[1]), "r"(a[2]), "r"(a[3]), "r"(b0), "r"(b1));
}

__device__ __forceinline__ void mma16816f(float c[4], const uint32_t a[4],
                                          uint32_t b0, uint32_t b1) {
    asm volatile(
        "mma.sync.aligned.m16n8k16.row.col.f32.f16.f16.f32 "
        "{%0,%1,%2,%3}, {%4,%5,%6,%7}, {%8,%9}, {%0,%1,%2,%3};"
        : "+f"(c[0]), "+f"(c[1]), "+f"(c[2]), "+f"(c[3])
        : "r"(a[0]), "r"(a[1]), "r"(a[2]), "r"(a[3]), "r"(b0), "r"(b1));
}

// ---------------- dense GEMM tiling ----------------
#define KT 32
#define NKT 32
#define ROWB 80
#define TILE_BG (128 * ROWB)
#define STAGE_B3 (4 * TILE_BG)
#define SMEM_GEMM3 (2 * STAGE_B3)      // 81920 (bf16 3-term path)
#define STAGE_B2 (3 * TILE_BG)
#define SMEM_GEMM2 (2 * STAGE_B2)      // 61440 (fp16 2-term path)

// ---- 3-term bf16 core (A hi/lo, B hi/lo) ----
__device__ __forceinline__ void stage_load3(
    uint32_t sbase, int s,
    const bf16* __restrict__ Ah, const bf16* __restrict__ Al,
    const bf16* __restrict__ Bh, const bf16* __restrict__ Bl,
    int kt, int tid)
{
    uint32_t st = sbase + s * STAGE_B3;
    const bf16* srcs[4] = {Ah, Al, Bh, Bl};
#pragma unroll
    for (int tI = 0; tI < 4; tI++) {
        const bf16* src = srcs[tI] + kt * KT;
        uint32_t dst = st + tI * TILE_BG;
#pragma unroll
        for (int i = 0; i < 2; i++) {
            int c = tid + i * 256;
            int row = c >> 2, seg = c & 3;
            cpa16(dst + row * ROWB + seg * 16, src + row * CCH + seg * 8);
        }
    }
}

__device__ __forceinline__ void gemm_core3(
    const bf16* __restrict__ Ah, const bf16* __restrict__ Al,
    const bf16* __restrict__ Bh, const bf16* __restrict__ Bl,
    uint32_t sbase, int tid, float acc[4][4][4])
{
#pragma unroll
    for (int i = 0; i < 4; i++)
#pragma unroll
        for (int j = 0; j < 4; j++)
#pragma unroll
            for (int r = 0; r < 4; r++) acc[i][j][r] = 0.f;

    const int lane = tid & 31, warp = tid >> 5;
    const int wm = warp >> 2, wn = warp & 3;

    stage_load3(sbase, 0, Ah, Al, Bh, Bl, 0, tid);
    CP_COMMIT();

    const uint32_t aoff = (uint32_t)((wm * 64 + ((lane >> 3) & 1) * 8 + (lane & 7)) * ROWB
                                     + ((lane >> 4) & 1) * 16);
    const uint32_t boff = (uint32_t)((wn * 32 + ((lane >> 4) & 1) * 8 + (lane & 7)) * ROWB
                                     + ((lane >> 3) & 1) * 16);

#pragma unroll 1
    for (int c = 0; c < NKT; c++) {
        CP_WAIT0();
        __syncthreads();
        if (c + 1 < NKT) {
            stage_load3(sbase, (c + 1) & 1, Ah, Al, Bh, Bl, c + 1, tid);
            CP_COMMIT();
        }
        const uint32_t st = sbase + (uint32_t)(c & 1) * STAGE_B3;
        const uint32_t aH = st + aoff;
        const uint32_t aL = st + TILE_BG + aoff;
        const uint32_t bH = st + 2 * TILE_BG + boff;
        const uint32_t bL = st + 3 * TILE_BG + boff;
#pragma unroll
        for (int ks = 0; ks < 2; ks++) {
            const uint32_t kc = ks * 32;
            uint32_t bh[2][4], bl[2][4];
#pragma unroll
            for (int p = 0; p < 2; p++) {
                ldsm4(bh[p], bH + p * 16 * ROWB + kc);
                ldsm4(bl[p], bL + p * 16 * ROWB + kc);
            }
#pragma unroll
            for (int mf = 0; mf < 4; mf++) {
                uint32_t ah4[4], al4[4];
                ldsm4(ah4, aH + mf * 16 * ROWB + kc);
                ldsm4(al4, aL + mf * 16 * ROWB + kc);
#pragma unroll
                for (int p = 0; p < 2; p++) {
                    mma16816(acc[mf][2 * p], ah4, bh[p][0], bh[p][1]);
                    mma16816(acc[mf][2 * p], ah4, bl[p][0], bl[p][1]);
                    mma16816(acc[mf][2 * p], al4, bh[p][0], bh[p][1]);
                    mma16816(acc[mf][2 * p + 1], ah4, bh[p][2], bh[p][3]);
                    mma16816(acc[mf][2 * p + 1], ah4, bl[p][2], bl[p][3]);
                    mma16816(acc[mf][2 * p + 1], al4, bh[p][2], bh[p][3]);
                }
            }
        }
    }
}

// ---- 2-term fp16 core (A hi/lo fp16, B single fp16) ----
__device__ __forceinline__ void stage_load2(
    uint32_t sbase, int s,
    const h16* __restrict__ Ah, const h16* __restrict__ Al,
    const h16* __restrict__ B, int kt, int tid)
{
    uint32_t st = sbase + s * STAGE_B2;
    const h16* srcs[3] = {Ah, Al, B};
#pragma unroll
    for (int tI = 0; tI < 3; tI++) {
        const h16* src = srcs[tI] + kt * KT;
        uint32_t dst = st + tI * TILE_BG;
#pragma unroll
        for (int i = 0; i < 2; i++) {
            int c = tid + i * 256;
            int row = c >> 2, seg = c & 3;
            cpa16(dst + row * ROWB + seg * 16, src + row * CCH + seg * 8);
        }
    }
}

__device__ __forceinline__ void gemm_core2(
    const h16* __restrict__ Ah, const h16* __restrict__ Al,
    const h16* __restrict__ B,
    uint32_t sbase, int tid, float acc[4][4][4])
{
#pragma unroll
    for (int i = 0; i < 4; i++)
#pragma unroll
        for (int j = 0; j < 4; j++)
#pragma unroll
            for (int r = 0; r < 4; r++) acc[i][j][r] = 0.f;

    const int lane = tid & 31, warp = tid >> 5;
    const int wm = warp >> 2, wn = warp & 3;

    stage_load2(sbase, 0, Ah, Al, B, 0, tid);
    CP_COMMIT();

    const uint32_t aoff = (uint32_t)((wm * 64 + ((lane >> 3) & 1) * 8 + (lane & 7)) * ROWB
                                     + ((lane >> 4) & 1) * 16);
    const uint32_t boff = (uint32_t)((wn * 32 + ((lane >> 4) & 1) * 8 + (lane & 7)) * ROWB
                                     + ((lane >> 3) & 1) * 16);

#pragma unroll 1
    for (int c = 0; c < NKT; c++) {
        CP_WAIT0();
        __syncthreads();
        if (c + 1 < NKT) {
            stage_load2(sbase, (c + 1) & 1, Ah, Al, B, c + 1, tid);
            CP_COMMIT();
        }
        const uint32_t st = sbase + (uint32_t)(c & 1) * STAGE_B2;
        const uint32_t aH = st + aoff;
        const uint32_t aL = st + TILE_BG + aoff;
        const uint32_t bB = st + 2 * TILE_BG + boff;
#pragma unroll
        for (int ks = 0; ks < 2; ks++) {
            const uint32_t kc = ks * 32;
            uint32_t bh[2][4];
#pragma unroll
            for (int p = 0; p < 2; p++)
                ldsm4(bh[p], bB + p * 16 * ROWB + kc);
#pragma unroll
            for (int mf = 0; mf < 4; mf++) {
                uint32_t ah4[4], al4[4];
                ldsm4(ah4, aH + mf * 16 * ROWB + kc);
                ldsm4(al4, aL + mf * 16 * ROWB + kc);
#pragma unroll
                for (int p = 0; p < 2; p++) {
                    mma16816f(acc[mf][2 * p], ah4, bh[p][0], bh[p][1]);
                    mma16816f(acc[mf][2 * p], al4, bh[p][0], bh[p][1]);
                    mma16816f(acc[mf][2 * p + 1], ah4, bh[p][2], bh[p][3]);
                    mma16816f(acc[mf][2 * p + 1], al4, bh[p][2], bh[p][3]);
                }
            }
        }
    }
}

// ---------------------------------------------------------------------------
// Prep kernels
// ---------------------------------------------------------------------------
__global__ __launch_bounds__(256) void convx_kernel(const float* __restrict__ x)
{
    int i = blockIdx.x * 256 + threadIdx.x;
    float4 v = ld4(x + i * 4);
    bf16 h0, h1, h2, h3, l0, l1, l2, l3;
    split_bf16(v.x, h0, l0);
    split_bf16(v.y, h1, l1);
    split_bf16(v.z, h2, l2);
    split_bf16(v.w, h3, l3);
    *(__nv_bfloat162*)&g_xh[i * 4] = mkbf2(h0, h1);
    *(__nv_bfloat162*)&g_xh[i * 4 + 2] = mkbf2(h2, h3);
    *(__nv_bfloat162*)&g_xl[i * 4] = mkbf2(l0, l1);
    *(__nv_bfloat162*)&g_xl[i * 4 + 2] = mkbf2(l2, l3);
    h16 fh0, fh1, fh2, fh3, fl0, fl1, fl2, fl3;
    split_f16(v.x, fh0, fl0);
    split_f16(v.y, fh1, fl1);
    split_f16(v.z, fh2, fl2);
    split_f16(v.w, fh3, fl3);
    *(__half2*)&g_fxh[i * 4] = mkh2(fh0, fh1);
    *(__half2*)&g_fxh[i * 4 + 2] = mkh2(fh2, fh3);
    *(__half2*)&g_fxl[i * 4] = mkh2(fl0, fl1);
    *(__half2*)&g_fxl[i * 4 + 2] = mkh2(fl2, fl3);
}

__global__ __launch_bounds__(256) void transw_kernel(
    const float* __restrict__ Wq, const float* __restrict__ Wk,
    const float* __restrict__ Wv, const float* __restrict__ Wo)
{
    __shared__ float tile[32][33];
    const int z = blockIdx.z;
    const float* src = (z == 0) ? Wq : (z == 1) ? Wk : (z == 2) ? Wv : Wo;

    int tx = threadIdx.x & 31, ty = threadIdx.x >> 5;
    int x = blockIdx.x * 32 + tx;
    int y = blockIdx.y * 32 + ty;
#pragma unroll
    for (int j = 0; j < 32; j += 8)
        tile[ty + j][tx] = src[(y + j) * CCH + x];
    __syncthreads();
    int x2 = blockIdx.y * 32 + tx;
    int y2 = blockIdx.x * 32 + ty;
#pragma unroll
    for (int j = 0; j < 32; j += 8) {
        float v = tile[tx][ty + j];
        int idx = (y2 + j) * CCH + x2;
        if (z < 2) {
            bf16 h, l;
            split_bf16(v, h, l);
            g_wth[z * CCH * CCH + idx] = h;
            g_wtl[z * CCH * CCH + idx] = l;
        } else if (z == 2) {
            g_wvf[idx] = __float2half_rn(v);
        } else {
            g_wof[idx] = __float2half_rn(v);
        }
    }
}

// ---------------------------------------------------------------------------
// Q/K projection (bf16 3-term): dst bf16 hi/lo [B][H][T][D]
// ---------------------------------------------------------------------------
__global__ __launch_bounds__(256, 2) void proj_qk_kernel()
{
    extern __shared__ char smem[];
    const int tid = threadIdx.x;
    const int m0 = blockIdx.y * 128;
    const int n0 = blockIdx.x * 128;
    const int z = blockIdx.z;

    const bf16* Ah = g_xh + m0 * CCH;
    const bf16* Al = g_xl + m0 * CCH;
    const bf16* Bh = g_wth + z * CCH * CCH + n0 * CCH;
    const bf16* Bl = g_wtl + z * CCH * CCH + n0 * CCH;
    bf16* dsth = (z == 0) ? g_qh : g_kh;
    bf16* dstl = (z == 0) ? g_ql : g_kl;

    float acc[4][4][4];
    gemm_core3(Ah, Al, Bh, Bl, smem_u32(smem), tid, acc);

    const int lane = tid & 31, warp = tid >> 5;
    const int wm = warp >> 2, wn = warp & 3;
    const int g = lane >> 2, t4 = lane & 3;
    const bool isq = (z == 0);
#pragma unroll
    for (int mf = 0; mf < 4; mf++)
#pragma unroll
        for (int nf = 0; nf < 4; nf++)
#pragma unroll
            for (int rr = 0; rr < 2; rr++) {
                int m = m0 + wm * 64 + mf * 16 + g + rr * 8;
                int n = n0 + wn * 32 + nf * 8 + t4 * 2;
                int bb = m >> 10, tt = m & 1023;
                int hh = n >> 6, dd = n & 63;
                float v0 = acc[mf][nf][rr * 2];
                float v1 = acc[mf][nf][rr * 2 + 1];
                if (isq) { v0 = nan2num(v0); v1 = nan2num(v1); }
                bf16 h0, h1, l0, l1;
                split_bf16(v0, h0, l0);
                split_bf16(v1, h1, l1);
                int idx = ((bb * HH + hh) * TT + tt) * DD + dd;
                *(__nv_bfloat162*)&dsth[idx] = mkbf2(h0, h1);
                *(__nv_bfloat162*)&dstl[idx] = mkbf2(l0, l1);
            }
}

// ---------------------------------------------------------------------------
// V projection (fp16 2-term): dst fp16 single [B][H][T][D]
// ---------------------------------------------------------------------------
__global__ __launch_bounds__(256, 2) void proj_v_kernel()
{
    extern __shared__ char smem[];
    const int tid = threadIdx.x;
    const int m0 = blockIdx.y * 128;
    const int n0 = blockIdx.x * 128;

    const h16* Ah = g_fxh + m0 * CCH;
    const h16* Al = g_fxl + m0 * CCH;
    const h16* B  = g_wvf + n0 * CCH;

    float acc[4][4][4];
    gemm_core2(Ah, Al, B, smem_u32(smem), tid, acc);

    const int lane = tid & 31, warp = tid >> 5;
    const int wm = warp >> 2, wn = warp & 3;
    const int g = lane >> 2, t4 = lane & 3;
#pragma unroll
    for (int mf = 0; mf < 4; mf++)
#pragma unroll
        for (int nf = 0; nf < 4; nf++)
#pragma unroll
            for (int rr = 0; rr < 2; rr++) {
                int m = m0 + wm * 64 + mf * 16 + g + rr * 8;
                int n = n0 + wn * 32 + nf * 8 + t4 * 2;
                int bb = m >> 10, tt = m & 1023;
                int hh = n >> 6, dd = n & 63;
                int idx = ((bb * HH + hh) * TT + tt) * DD + dd;
                *(__half2*)&g_vf[idx] =
                    __floats2half2_rn(acc[mf][nf][rr * 2], acc[mf][nf][rr * 2 + 1]);
            }
}

// ---------------------------------------------------------------------------
// Output GEMM (fp16 2-term): out = attn @ Wo
// ---------------------------------------------------------------------------
__global__ __launch_bounds__(256, 2) void out_tc_kernel(float* __restrict__ out)
{
    extern __shared__ char smem[];
    const int tid = threadIdx.x;
    const int m0 = blockIdx.y * 128;
    const int n0 = blockIdx.x * 128;

    const h16* Ah = g_ah + m0 * CCH;
    const h16* Al = g_al + m0 * CCH;
    const h16* B  = g_wof + n0 * CCH;

    float acc[4][4][4];
    gemm_core2(Ah, Al, B, smem_u32(smem), tid, acc);

    const int lane = tid & 31, warp = tid >> 5;
    const int wm = warp >> 2, wn = warp & 3;
    const int g = lane >> 2, t4 = lane & 3;
#pragma unroll
    for (int mf = 0; mf < 4; mf++)
#pragma unroll
        for (int nf = 0; nf < 4; nf++)
#pragma unroll
            for (int rr = 0; rr < 2; rr++) {
                int m = m0 + wm * 64 + mf * 16 + g + rr * 8;
                int n = n0 + wn * 32 + nf * 8 + t4 * 2;
                float2 v;
                v.x = acc[mf][nf][rr * 2];
                v.y = acc[mf][nf][rr * 2 + 1];
                *(float2*)&out[m * CCH + n] = v;
            }
}

// ---------------------------------------------------------------------------
// Attention: CTA = (b, h, 128-query tile), 8 warps; warp owns 16 full rows.
// Phase A bf16 3-term (selection-safe); Phase C fp16 2-term (P split, V single).
// ---------------------------------------------------------------------------
#define QSTR 144
#define TILE_A (64 * QSTR)
#define AQH 0
#define AQL (128 * QSTR)
#define AKV (2 * 128 * QSTR)
#define SMEM_ATTN (AKV + 2 * 3 * TILE_A)   // 92160

// Exact 32nd-largest (thr) and max (mx) of 64 values spread 16/lane on a quad.
__device__ __forceinline__ void sel64(const float s[16], float& thr, float& mx)
{
    const unsigned FULL = 0xffffffffu;
    const int t4 = threadIdx.x & 3;
    float v[16];
#pragma unroll
    for (int i = 0; i < 16; i++) v[i] = s[i];
#pragma unroll
    for (int size = 2; size <= 16; size <<= 1) {
#pragma unroll
        for (int stride = size >> 1; stride >= 1; stride >>= 1) {
#pragma unroll
            for (int i = 0; i < 16; i++) {
                int j = i ^ stride;
                if (j > i) {
                    bool up = ((i & size) == 0) || (size == 16);
                    float lo = fminf(v[i], v[j]);
                    float hi = fmaxf(v[i], v[j]);
                    v[i] = up ? lo : hi;
                    v[j] = up ? hi : lo;
                }
            }
        }
    }
    {
        const bool lowh = ((t4 & 1) == 0);
#pragma unroll
        for (int i = 0; i < 8; i++) {
            float vi = v[i], vo = v[15 - i];
            float a = __shfl_xor_sync(FULL, vo, 1);
            float b = __shfl_xor_sync(FULL, vi, 1);
            v[i]      = lowh ? fminf(vi, a) : fmaxf(vi, a);
            v[15 - i] = lowh ? fminf(vo, b) : fmaxf(vo, b);
        }
#pragma unroll
        for (int stride = 8; stride >= 1; stride >>= 1) {
#pragma unroll
            for (int i = 0; i < 16; i++) {
                int j = i ^ stride;
                if (j > i) {
                    float lo = fminf(v[i], v[j]);
                    float hi = fmaxf(v[i], v[j]);
                    v[i] = lo;
                    v[j] = hi;
                }
            }
        }
    }
    float mn = 1e30f, mmx = -1e30f;
#pragma unroll
    for (int i = 0; i < 8; i++) {
        float vi = v[i], vo = v[15 - i];
        float a = __shfl_xor_sync(FULL, vo, 3);
        float b = __shfl_xor_sync(FULL, vi, 3);
        float c0 = fmaxf(vi, a);
        float c1 = fmaxf(vo, b);
        mn = fminf(mn, fminf(c0, c1));
        mmx = fmaxf(mmx, fmaxf(c0, c1));
    }
    mn = fminf(mn, __shfl_xor_sync(FULL, mn, 1));
    mmx = fmaxf(mmx, __shfl_xor_sync(FULL, mmx, 1));
    thr = mn;
    mx = mmx;
}

__device__ __forceinline__ void kv_load(
    uint32_t stage, const bf16* __restrict__ kh, const bf16* __restrict__ kl,
    const h16* __restrict__ vf, int tid)
{
#pragma unroll
    for (int i = 0; i < 6; i++) {
        int flat = i * 256 + tid;
        int tile = flat >> 9;      // 0..2
        int rem = flat & 511;
        int row = rem >> 3, seg = rem & 7;
        const void* src = (tile == 0) ? (const void*)(kh + row * 64 + seg * 8)
                        : (tile == 1) ? (const void*)(kl + row * 64 + seg * 8)
                                      : (const void*)(vf + row * 64 + seg * 8);
        cpa16(stage + tile * TILE_A + row * QSTR + seg * 16, src);
    }
}

__global__ __launch_bounds__(256, 2) void attn_kernel(
    const float* __restrict__ imp, const float* __restrict__ temps)
{
    extern __shared__ char smc[];
    const uint32_t sb = smem_u32(smc);

    const int qt = blockIdx.x, h = blockIdx.y, b = blockIdx.z;
    const int tid = threadIdx.x;
    const int lane = tid & 31, warp = tid >> 5;
    const int g = lane >> 2, t4 = lane & 3;
    const unsigned FULL = 0xffffffffu;

    const int hbase = ((b * HH + h) * TT) * DD;
    const int qb = hbase + qt * 128 * DD;

#pragma unroll
    for (int i = 0; i < 8; i++) {
        int flat = i * 256 + tid;
        int half = flat >> 10;
        int rem = flat & 1023;
        int row = rem >> 3, seg = rem & 7;
        const bf16* src = (half ? g_ql : g_qh) + qb + row * 64 + seg * 8;
        cpa16(sb + (half ? AQL : AQH) + row * QSTR + seg * 16, src);
    }
    kv_load(sb + AKV, g_kh + hbase, g_kl + hbase, g_vf + hbase, tid);
    CP_COMMIT();

    const int r0 = warp * 16 + g;
    const int r1 = r0 + 8;
    float w0, w1;
    {
        float tv = temps[b * HH + h];
        tv = fminf(fmaxf(tv, 0.1f), 100.f);
        float sc = SCALE_F / tv;
        float iv0 = imp[(b * TT + qt * 128 + r0) * HH + h];
        float iv1 = imp[(b * TT + qt * 128 + r1) * HH + h];
        float s0 = 1.f / (1.f + __expf(-iv0));
        float s1 = 1.f / (1.f + __expf(-iv1));
        w0 = sc / (1.f + __expf(-(s0 - 0.5f) * 10.f));
        w1 = sc / (1.f + __expf(-(s1 - 0.5f) * 10.f));
    }

    const uint32_t aoff = (uint32_t)((warp * 16 + ((lane >> 3) & 1) * 8 + (lane & 7)) * QSTR
                                     + ((lane >> 4) & 1) * 16);
    const uint32_t koff = (uint32_t)((((lane >> 4) & 1) * 8 + (lane & 7)) * QSTR
                                     + ((lane >> 3) & 1) * 16);
    const uint32_t voff = (uint32_t)((((lane >> 3) & 1) * 8 + (lane & 7)) * QSTR
                                     + ((lane >> 4) & 1) * 16);

    float O[8][4];
#pragma unroll
    for (int i = 0; i < 8; i++)
#pragma unroll
        for (int r = 0; r < 4; r++) O[i][r] = 0.f;
    float psum0 = 0.f, psum1 = 0.f;

#pragma unroll 1
    for (int c = 0; c < NKC; c++) {
        CP_WAIT0();
        __syncthreads();
        const uint32_t cur = sb + AKV + (uint32_t)(c & 1) * (3 * TILE_A);
        if (c + 1 < NKC) {
            int off = (c + 1) * 64 * DD;
            kv_load(sb + AKV + (uint32_t)((c + 1) & 1) * (3 * TILE_A),
                    g_kh + hbase + off, g_kl + hbase + off,
                    g_vf + hbase + off, tid);
            CP_COMMIT();
        }

        // Phase A: S = Q K^T (bf16 3-term)
        float acc[8][4];
#pragma unroll
        for (int i = 0; i < 8; i++)
#pragma unroll
            for (int r = 0; r < 4; r++) acc[i][r] = 0.f;
#pragma unroll
        for (int ks = 0; ks < 4; ks++) {
            uint32_t qh4[4], ql4[4];
            ldsm4(qh4, sb + AQH + aoff + ks * 32);
            ldsm4(ql4, sb + AQL + aoff + ks * 32);
#pragma unroll
            for (int nf = 0; nf < 4; nf++) {
                uint32_t kh4[4], kl4[4];
                ldsm4(kh4, cur + koff + nf * 16 * QSTR + ks * 32);
                ldsm4(kl4, cur + TILE_A + koff + nf * 16 * QSTR + ks * 32);
                mma16816(acc[2 * nf], qh4, kh4[0], kh4[1]);
                mma16816(acc[2 * nf], qh4, kl4[0], kl4[1]);
                mma16816(acc[2 * nf], ql4, kh4[0], kh4[1]);
                mma16816(acc[2 * nf + 1], qh4, kh4[2], kh4[3]);
                mma16816(acc[2 * nf + 1], qh4, kl4[2], kl4[3]);
                mma16816(acc[2 * nf + 1], ql4, kh4[2], kh4[3]);
            }
        }
#pragma unroll
        for (int nf = 0; nf < 8; nf++) {
            acc[nf][0] *= w0;
            acc[nf][1] *= w0;
            acc[nf][2] *= w1;
            acc[nf][3] *= w1;
        }

        // Phase B: register-resident top-32 + softmax
#pragma unroll
        for (int rh = 0; rh < 2; rh++) {
            const int jo = rh * 2;
            float s[16];
#pragma unroll
            for (int nf = 0; nf < 8; nf++) {
                s[2 * nf] = acc[nf][jo];
                s[2 * nf + 1] = acc[nf][jo + 1];
            }
            float thr, mx;
            sel64(s, thr, mx);
            mx = fmaxf(mx, 0.f);
            float e[16];
            float sum = 0.f;
#pragma unroll
            for (int i = 0; i < 16; i++) {
                float m = (s[i] >= thr) ? s[i] : 0.f;
                e[i] = __expf(m - mx);
                sum += e[i];
            }
            sum += __shfl_xor_sync(FULL, sum, 1);
            sum += __shfl_xor_sync(FULL, sum, 2);
            float inv = 1.f / fmaxf(sum, 1e-6f);
#pragma unroll
            for (int nf = 0; nf < 8; nf++) {
                acc[nf][jo] = e[2 * nf] * inv;
                acc[nf][jo + 1] = e[2 * nf + 1] * inv;
            }
            if (rh == 0) psum0 += sum * inv;
            else         psum1 += sum * inv;
        }

        // Phase C: O += P V (P fp16 exact split, V fp16 single -> 4 MMAs/nf-pair)
#pragma unroll
        for (int ks = 0; ks < 4; ks++) {
            uint32_t ph[4], pl[4];
            {
                h16 h00, l00, h01, l01, h02, l02, h03, l03;
                h16 h10, l10, h11, l11, h12, l12, h13, l13;
                split_f16(acc[2 * ks][0], h00, l00);
                split_f16(acc[2 * ks][1], h01, l01);
                split_f16(acc[2 * ks + 1][0], h02, l02);
                split_f16(acc[2 * ks + 1][1], h03, l03);
                split_f16(acc[2 * ks][2], h10, l10);
                split_f16(acc[2 * ks][3], h11, l11);
                split_f16(acc[2 * ks + 1][2], h12, l12);
                split_f16(acc[2 * ks + 1][3], h13, l13);
                ph[0] = pkh(h00, h01); ph[1] = pkh(h10, h11);
                ph[2] = pkh(h02, h03); ph[3] = pkh(h12, h13);
                pl[0] = pkh(l00, l01); pl[1] = pkh(l10, l11);
                pl[2] = pkh(l02, l03); pl[3] = pkh(l12, l13);
            }
#pragma unroll
            for (int nf = 0; nf < 4; nf++) {
                uint32_t vf4[4];
                ldsm4t(vf4, cur + 2 * TILE_A + voff + ks * 16 * QSTR + nf * 32);
                mma16816f(O[2 * nf], ph, vf4[0], vf4[1]);
                mma16816f(O[2 * nf], pl, vf4[0], vf4[1]);
                mma16816f(O[2 * nf + 1], ph, vf4[2], vf4[3]);
                mma16816f(O[2 * nf + 1], pl, vf4[2], vf4[3]);
            }
        }
    }

    // Epilogue: normalize, nan2num, fp16 split -> g_ah/g_al
    const float inv0 = 1.f / fmaxf(psum0, 1e-6f);
    const float inv1 = 1.f / fmaxf(psum1, 1e-6f);
    const int t0 = qt * 128 + r0;
    const int t1 = qt * 128 + r1;
#pragma unroll
    for (int nf = 0; nf < 8; nf++) {
        int colb = h * 64 + nf * 8 + t4 * 2;
        float v0 = nan2num(O[nf][0] * inv0);
        float v1 = nan2num(O[nf][1] * inv0);
        float v2 = nan2num(O[nf][2] * inv1);
        float v3 = nan2num(O[nf][3] * inv1);
        h16 h0, l0, h1, l1, h2, l2, h3, l3;
        split_f16(v0, h0, l0);
        split_f16(v1, h1, l1);
        split_f16(v2, h2, l2);
        split_f16(v3, h3, l3);
        int i0 = (b * TT + t0) * CCH + colb;
        int i1 = (b * TT + t1) * CCH + colb;
        *(__half2*)&g_ah[i0] = mkh2(h0, h1);
        *(__half2*)&g_al[i0] = mkh2(l0, l1);
        *(__half2*)&g_ah[i1] = mkh2(h2, h3);
        *(__half2*)&g_al[i1] = mkh2(l2, l3);
    }
}

// ---------------------------------------------------------------------------
extern "C" void kernel_launch(void* const* d_in, const int* in_sizes, int n_in,
                              void* d_out, int out_size)
{
    const float* x     = (const float*)d_in[0];
    const float* imp   = (const float*)d_in[1];
    const float* temps = (const float*)d_in[2];
    const float* Wq    = (const float*)d_in[3];
    const float* Wk    = (const float*)d_in[4];
    const float* Wv    = (const float*)d_in[5];
    const float* Wo    = (const float*)d_in[6];
    float* out = (float*)d_out;

    cudaFuncSetAttribute(attn_kernel,
                         cudaFuncAttributeMaxDynamicSharedMemorySize, SMEM_ATTN);
    cudaFuncSetAttribute(proj_qk_kernel,
                         cudaFuncAttributeMaxDynamicSharedMemorySize, SMEM_GEMM3);
    cudaFuncSetAttribute(proj_v_kernel,
                         cudaFuncAttributeMaxDynamicSharedMemorySize, SMEM_GEMM2);
    cudaFuncSetAttribute(out_tc_kernel,
                         cudaFuncAttributeMaxDynamicSharedMemorySize, SMEM_GEMM2);

    convx_kernel<<<BB * TT * CCH / 1024, 256>>>(x);
    transw_kernel<<<dim3(32, 32, 4), 256>>>(Wq, Wk, Wv, Wo);
    proj_qk_kernel<<<dim3(8, 32, 2), 256, SMEM_GEMM3>>>();
    proj_v_kernel<<<dim3(8, 32), 256, SMEM_GEMM2>>>();
    attn_kernel<<<dim3(8, HH, BB), 256, SMEM_ATTN>>>(imp, temps);
    out_tc_kernel<<<dim3(8, 32), 256, SMEM_GEMM2>>>(out);
}